// round 13
// baseline (speedup 1.0000x reference)
#include <cuda_runtime.h>
#include <cuda_fp16.h>
#include <cstdint>
#include <math.h>

#define DIM 2048
#define TLEN 2048
#define NB 4
#define HD 128
#define NH 16
#define ROWS (NB*TLEN)   // 8192

// ---------------- scratch (device globals; no allocations allowed) ----------------
__device__ float  g_qkv[(size_t)ROWS*3*DIM];       // fp32 qkv (attn + qkrot path)
__device__ __half g_xnh[(size_t)ROWS*DIM];         // normalized activations (half)
__device__ __half g_attnh[(size_t)ROWS*DIM];       // attention output (half)
__device__ __half g_hh[(size_t)ROWS*4*DIM];        // mlp hidden (half)
__device__ __half g_wqkvh[(size_t)3*DIM*DIM];      // half weights
__device__ __half g_owh[(size_t)DIM*DIM];
__device__ __half g_w1h[(size_t)4*DIM*DIM];
__device__ __half g_w2h[(size_t)4*DIM*DIM];
__device__ float2 g_trig[(size_t)TLEN*32];         // (cos,sin) per (t, freq-lane)

// ---------------- helpers ----------------
__device__ __forceinline__ void cp16h(__half* s, const __half* g){
  uint32_t sa = (uint32_t)__cvta_generic_to_shared(s);
  asm volatile("cp.async.cg.shared.global [%0], [%1], 16;\n" :: "r"(sa), "l"(g));
}
__device__ __forceinline__ void cp_commit(){ asm volatile("cp.async.commit_group;\n" ::: "memory"); }
template<int N> __device__ __forceinline__ void cp_wait(){
  asm volatile("cp.async.wait_group %0;\n" :: "n"(N) : "memory");
}

// fp16 mma: D(16x8,f32) += A(16x16,f16,row) * B(16x8,f16,col)
__device__ __forceinline__ void mma16(float* d, const uint32_t* a, const uint32_t* b){
  asm volatile(
    "mma.sync.aligned.m16n8k16.row.col.f32.f16.f16.f32 "
    "{%0,%1,%2,%3}, {%4,%5,%6,%7}, {%8,%9}, {%0,%1,%2,%3};\n"
    : "+f"(d[0]), "+f"(d[1]), "+f"(d[2]), "+f"(d[3])
    : "r"(a[0]), "r"(a[1]), "r"(a[2]), "r"(a[3]), "r"(b[0]), "r"(b[1]));
}

__device__ __forceinline__ void ldsm4(uint32_t* r, uint32_t addr){
  asm volatile("ldmatrix.sync.aligned.m8n8.x4.shared.b16 {%0,%1,%2,%3}, [%4];"
    : "=r"(r[0]), "=r"(r[1]), "=r"(r[2]), "=r"(r[3]) : "r"(addr));
}

// ---------------- rotary trig table (computed once; same bits as before) ----------------
__global__ void __launch_bounds__(256) trig_k(float2* __restrict__ tb){
  int i = blockIdx.x * 256 + threadIdx.x;       // 65536 entries
  int t = i >> 5, l = i & 31;
  double fd = pow(1.0e-4, (double)l * (1.0/31.0));
  float thf = (float)t * (float)fd;
  tb[i] = make_float2((float)cos((double)thf), (float)sin((double)thf));
}

// ---------------- fp32 -> fp16 bulk convert ----------------
__global__ void __launch_bounds__(256) f2h_k(const float4* __restrict__ in,
                                             __half2* __restrict__ out, int n4){
  int i = blockIdx.x * 256 + threadIdx.x;
  if (i < n4){
    float4 v = in[i];
    out[2*i]   = __floats2half2_rn(v.x, v.y);
    out[2*i+1] = __floats2half2_rn(v.z, v.w);
  }
}

// ---------------- RMSNorm over last dim (2048), half output ----------------
__global__ void __launch_bounds__(256) rmsnorm_k(const float* __restrict__ x, __half* __restrict__ o){
  __shared__ float red[256];
  size_t base = (size_t)blockIdx.x * DIM;
  const float4* xv = (const float4*)(x + base);
  __half2* ov = (__half2*)(o + base);
  int tid = threadIdx.x;
  float4 a = xv[tid], b = xv[tid + 256];
  float ss = a.x*a.x + a.y*a.y + a.z*a.z + a.w*a.w
           + b.x*b.x + b.y*b.y + b.z*b.z + b.w*b.w;
  red[tid] = ss;
  __syncthreads();
  #pragma unroll
  for (int s = 128; s > 0; s >>= 1){
    if (tid < s) red[tid] += red[tid + s];
    __syncthreads();
  }
  float sc = 1.0f / sqrtf(red[0] * (1.0f/DIM) + 1e-6f);
  ov[2*tid]       = __floats2half2_rn(a.x*sc, a.y*sc);
  ov[2*tid+1]     = __floats2half2_rn(a.z*sc, a.w*sc);
  ov[2*(tid+256)]   = __floats2half2_rn(b.x*sc, b.y*sc);
  ov[2*(tid+256)+1] = __floats2half2_rn(b.z*sc, b.w*sc);
}

// ---------------- QK head-norm + rotary (table-driven) + emit k,v outputs ----------------
__global__ void __launch_bounds__(256) qkrot_k(float* __restrict__ qkv,
                                               const float2* __restrict__ trig,
                                               float* __restrict__ out_k,
                                               float* __restrict__ out_v){
  int row = blockIdx.x;
  int t = row & (TLEN - 1);
  int tid = threadIdx.x, w = tid >> 5, l = tid & 31;

  float2 cssn = trig[(t << 5) | l];
  float cs = cssn.x, sn = cssn.y;

  float* base = qkv + (size_t)row * (3*DIM);
  for (int hh = w; hh < 32; hh += 8){
    int isk = (hh >= 16);
    int h = hh & 15;
    float* p = base + (isk ? DIM : 0) + h*HD;
    float x0 = p[l], x1 = p[l+32], x2 = p[l+64], x3 = p[l+96];
    float ss = x0*x0 + x1*x1 + x2*x2 + x3*x3;
    #pragma unroll
    for (int o = 16; o; o >>= 1) ss += __shfl_xor_sync(~0u, ss, o);
    float sc = 1.0f / sqrtf(ss * (1.0f/HD) + 1e-6f);
    x0 *= sc; x1 *= sc; x2 *= sc; x3 *= sc;
    float y0 =  x0*cs + x2*sn;
    float y2 = -x0*sn + x2*cs;
    p[l] = y0; p[l+32] = x1; p[l+64] = y2; p[l+96] = x3;
    if (isk){
      float* ok = out_k + (size_t)row*DIM + h*HD;
      ok[l] = y0; ok[l+32] = x1; ok[l+64] = y2; ok[l+96] = x3;
    }
  }
  const float* vsrc = base + 2*DIM;
  float* vo = out_v + (size_t)row*DIM;
  for (int i = tid; i < DIM; i += 256) vo[i] = vsrc[i];
}

// ---------------- fp16 GEMM: C[M,N] = A[M,K] @ B[N,K]^T ----------------
// CTA tile 128x256, 8 warps 2x4, warp tile 64x64. K-stage 64, 3-buffer cp.async ring,
// lookahead 2, ONE __syncthreads per stage, ldmatrix fragment loads.
// EPI 0: plain fp32 store. EPI 1: fp32 C = res + acc*svec[col]. EPI 2: half C = rn(relu(acc)^2)
template<int EPI>
__global__ void __launch_bounds__(256, 1) hgemm(
    const __half* __restrict__ A, const __half* __restrict__ B, void* __restrict__ Cv,
    int M, int N, int K, const float* __restrict__ res, const float* __restrict__ svec)
{
  extern __shared__ __half smh[];
  const int SH = 72;                        // half stride: 8 rows span all 32 banks
  __half* As = smh;                         // [3][128][72]
  __half* Bs = smh + 3*128*SH;              // [3][256][72]
  int tid = threadIdx.x;
  int warp = tid >> 5, lane = tid & 31;
  int wm = (warp >> 2) * 64, wn = (warp & 3) * 64;
  int g = lane >> 2, tg = lane & 3;
  int bm = blockIdx.y * 128, bn = blockIdx.x * 256;
  const __half* gA = A + (size_t)bm * K;
  const __half* gB = B + (size_t)bn * K;
  int lrow = tid >> 3, lseg = (tid & 7) * 8;

  // ldmatrix per-lane address components
  uint32_t sA = (uint32_t)__cvta_generic_to_shared(As);
  uint32_t sB = sA + 3*128*SH*2;
  uint32_t a_row  = (lane & 7) + ((lane >> 3) & 1) * 8;
  uint32_t a_koff = (lane >> 4) * 8;
  uint32_t b_row  = (lane & 7) + (lane >> 4) * 8;
  uint32_t b_koff = ((lane >> 3) & 1) * 8;
  uint32_t awo = (uint32_t)(wm + a_row) * (SH*2) + a_koff*2;
  uint32_t bwo = (uint32_t)(wn + b_row) * (SH*2) + b_koff*2;

  float acc[4][8][4];
  #pragma unroll
  for (int i = 0; i < 4; i++)
    #pragma unroll
    for (int j = 0; j < 8; j++)
      #pragma unroll
      for (int q = 0; q < 4; q++) acc[i][j][q] = 0.f;

  auto load_stage = [&](int s, int buf){
    int k0 = s * 64;
    __half* as = As + buf * (128*SH);
    __half* bs = Bs + buf * (256*SH);
    #pragma unroll
    for (int i = 0; i < 4; i++){
      int r = lrow + i*32;
      cp16h(as + r*SH + lseg, gA + (size_t)r*K + k0 + lseg);
    }
    #pragma unroll
    for (int i = 0; i < 8; i++){
      int r = lrow + i*32;
      cp16h(bs + r*SH + lseg, gB + (size_t)r*K + k0 + lseg);
    }
  };

  int S = K / 64;
  load_stage(0, 0); cp_commit();
  load_stage(1, 1); cp_commit();

  int buf = 0, nb = 2;
  for (int s = 0; s < S; s++){
    if (s + 1 < S) cp_wait<1>(); else cp_wait<0>();
    __syncthreads();                       // stage s resident; compute(s-1) retired by all warps
    if (s + 2 < S){                        // load into buffer (s+2)%3 == (s-1)%3 (now free)
      load_stage(s + 2, nb);
      cp_commit();
    }
    uint32_t aw = sA + (uint32_t)buf*(128*SH*2) + awo;
    uint32_t bw = sB + (uint32_t)buf*(256*SH*2) + bwo;
    #pragma unroll
    for (int kk = 0; kk < 4; kk++){
      uint32_t af[4][4], bf[8][2];
      #pragma unroll
      for (int mt = 0; mt < 4; mt++)
        ldsm4(af[mt], aw + (uint32_t)mt*(16*SH*2) + kk*32);
      #pragma unroll
      for (int p = 0; p < 4; p++){
        uint32_t r[4];
        ldsm4(r, bw + (uint32_t)p*(16*SH*2) + kk*32);
        bf[2*p][0]   = r[0]; bf[2*p][1]   = r[1];
        bf[2*p+1][0] = r[2]; bf[2*p+1][1] = r[3];
      }
      #pragma unroll
      for (int mt = 0; mt < 4; mt++)
        #pragma unroll
        for (int nt = 0; nt < 8; nt++)
          mma16(acc[mt][nt], af[mt], bf[nt]);
    }
    buf = (buf + 1) % 3;
    nb  = (nb + 1) % 3;
  }

  // epilogue
  #pragma unroll
  for (int mt = 0; mt < 4; mt++){
    int r0 = bm + wm + mt*16 + g;
    #pragma unroll
    for (int nt = 0; nt < 8; nt++){
      int c0 = bn + wn + nt*8 + tg*2;
      float a0 = acc[mt][nt][0], a1 = acc[mt][nt][1];
      float a2 = acc[mt][nt][2], a3 = acc[mt][nt][3];
      if (EPI == 0){
        float* C = (float*)Cv;
        *(float2*)(C + (size_t)r0*N + c0)     = make_float2(a0, a1);
        *(float2*)(C + (size_t)(r0+8)*N + c0) = make_float2(a2, a3);
      } else if (EPI == 1){
        float* C = (float*)Cv;
        float s0 = svec[c0], s1 = svec[c0+1];
        const float* rr0 = res + (size_t)r0*N + c0;
        const float* rr1 = res + (size_t)(r0+8)*N + c0;
        *(float2*)(C + (size_t)r0*N + c0)     = make_float2(rr0[0] + a0*s0, rr0[1] + a1*s1);
        *(float2*)(C + (size_t)(r0+8)*N + c0) = make_float2(rr1[0] + a2*s0, rr1[1] + a3*s1);
      } else {
        __half* C = (__half*)Cv;
        float v0 = fmaxf(a0, 0.f), v1 = fmaxf(a1, 0.f);
        float v2 = fmaxf(a2, 0.f), v3 = fmaxf(a3, 0.f);
        *(__half2*)(C + (size_t)r0*N + c0)     = __floats2half2_rn(v0*v0, v1*v1);
        *(__half2*)(C + (size_t)(r0+8)*N + c0) = __floats2half2_rn(v2*v2, v3*v3);
      }
    }
  }
}

// ---------------- causal flash attention (fp16 mma), Qtile=128, Ktile=64 ----------------
// Register-prefetch + double-buffered K/V smem tiles; ONE __syncthreads per kt.
// smem (halves): Qs 128x136, Ks[2] 64x136, Vt[2] 128x72, Ps 8 warps x 16x72
__global__ void __launch_bounds__(256) attn_k(const float* __restrict__ qkv, __half* __restrict__ outp)
{
  extern __shared__ __half smah[];
  const int SQ = 136, SV = 72, SP = 72;
  __half* Qs = smah;                        // 128*136
  __half* Ks = Qs + 128*SQ;                 // 2 x 64*136
  __half* Vt = Ks + 2*64*SQ;                // 2 x 128*72  [d][key]
  __half* Ps = Vt + 2*128*SV;               // 8*16*72
  int tid = threadIdx.x, warp = tid >> 5, lane = tid & 31;
  int g = lane >> 2, tg = lane & 3;
  int qt = blockIdx.x;
  int bh = blockIdx.y; int b = bh >> 4, h = bh & 15;
  const size_t rs = 3*DIM;

  const float* qbase = qkv + (size_t)(b*TLEN + qt*128)*rs + h*HD;
  for (int i = tid; i < 128*32; i += 256){
    int r = i >> 5, c4 = (i & 31) * 4;
    float4 v = *(const float4*)(qbase + (size_t)r*rs + c4);
    *(__half2*)(Qs + r*SQ + c4)     = __floats2half2_rn(v.x, v.y);
    *(__half2*)(Qs + r*SQ + c4 + 2) = __floats2half2_rn(v.z, v.w);
  }

  float o[16][4];
  #pragma unroll
  for (int i = 0; i < 16; i++){ o[i][0]=0.f; o[i][1]=0.f; o[i][2]=0.f; o[i][3]=0.f; }
  float m0 = -1e30f, m1 = -1e30f, l0 = 0.f, l1 = 0.f;
  int ktn = 2*qt + 2;
  int qr0 = qt*128 + warp*16;
  const float SCL = 0.08838834764831845f;

  // register prefetch staging
  float4 kreg[8];
  float4 vreg[4][2];
  auto load_tile = [&](int kt){
    const float* kb = qkv + (size_t)(b*TLEN + kt*64)*rs + DIM + h*HD;
    const float* vb = kb + DIM;
    #pragma unroll
    for (int u = 0; u < 8; u++){
      int i = tid + u*256;
      int r = i >> 5, c4 = (i & 31) * 4;
      kreg[u] = *(const float4*)(kb + (size_t)r*rs + c4);
    }
    #pragma unroll
    for (int u = 0; u < 4; u++){
      int i = tid + u*256;
      int p = i >> 5, ln = i & 31;
      int r0 = 2*p, c4 = ln*4;
      vreg[u][0] = *(const float4*)(vb + (size_t)r0*rs + c4);
      vreg[u][1] = *(const float4*)(vb + (size_t)(r0+1)*rs + c4);
    }
  };
  auto store_tile = [&](int bi){
    __half* Ksb = Ks + bi*(64*SQ);
    __half* Vtb = Vt + bi*(128*SV);
    #pragma unroll
    for (int u = 0; u < 8; u++){
      int i = tid + u*256;
      int r = i >> 5, c4 = (i & 31) * 4;
      *(__half2*)(Ksb + r*SQ + c4)     = __floats2half2_rn(kreg[u].x, kreg[u].y);
      *(__half2*)(Ksb + r*SQ + c4 + 2) = __floats2half2_rn(kreg[u].z, kreg[u].w);
    }
    #pragma unroll
    for (int u = 0; u < 4; u++){
      int i = tid + u*256;
      int p = i >> 5, ln = i & 31;
      int r0 = 2*p, c4 = ln*4;
      float a0[4] = {vreg[u][0].x, vreg[u][0].y, vreg[u][0].z, vreg[u][0].w};
      float a1[4] = {vreg[u][1].x, vreg[u][1].y, vreg[u][1].z, vreg[u][1].w};
      #pragma unroll
      for (int j = 0; j < 4; j++){
        int jj = (j + ln) & 3;
        *(__half2*)(Vtb + (c4 + jj)*SV + r0) = __floats2half2_rn(a0[jj], a1[jj]);
      }
    }
  };

  load_tile(0);
  for (int kt = 0; kt < ktn; kt++){
    int bi = kt & 1;
    // Race-safety: buf bi was last READ by compute(kt-2), which every warp finished
    // before arriving at iteration (kt-1)'s __syncthreads. Compute(kt-1) (possibly
    // in flight on other warps) reads buf bi^1 — disjoint. Single sync per iter.
    store_tile(bi);
    __syncthreads();
    if (kt + 1 < ktn) load_tile(kt + 1);   // overlap gmem latency with compute below
    if (kt*64 > qr0 + 15) continue;

    const __half* Ksb = Ks + bi*(64*SQ);
    const __half* Vtb = Vt + bi*(128*SV);

    float sacc[8][4];
    #pragma unroll
    for (int nt = 0; nt < 8; nt++){ sacc[nt][0]=0.f; sacc[nt][1]=0.f; sacc[nt][2]=0.f; sacc[nt][3]=0.f; }
    #pragma unroll
    for (int kk = 0; kk < 8; kk++){
      uint32_t af[4];
      const __half* qp = Qs + (warp*16 + g)*SQ + kk*16 + tg*2;
      af[0] = *(const uint32_t*)(qp);
      af[1] = *(const uint32_t*)(qp + 8*SQ);
      af[2] = *(const uint32_t*)(qp + 8);
      af[3] = *(const uint32_t*)(qp + 8*SQ + 8);
      #pragma unroll
      for (int nt = 0; nt < 8; nt++){
        uint32_t bf[2];
        const __half* kp = Ksb + (nt*8 + g)*SQ + kk*16 + tg*2;
        bf[0] = *(const uint32_t*)(kp);
        bf[1] = *(const uint32_t*)(kp + 8);
        mma16(sacc[nt], af, bf);
      }
    }

    int q0 = qr0 + g, q1 = q0 + 8;
    float mx0 = -1e30f, mx1 = -1e30f;
    #pragma unroll
    for (int nt = 0; nt < 8; nt++){
      int c = kt*64 + nt*8 + tg*2;
      sacc[nt][0] = (c     <= q0) ? sacc[nt][0]*SCL : -1e30f;
      sacc[nt][1] = (c + 1 <= q0) ? sacc[nt][1]*SCL : -1e30f;
      sacc[nt][2] = (c     <= q1) ? sacc[nt][2]*SCL : -1e30f;
      sacc[nt][3] = (c + 1 <= q1) ? sacc[nt][3]*SCL : -1e30f;
      mx0 = fmaxf(mx0, fmaxf(sacc[nt][0], sacc[nt][1]));
      mx1 = fmaxf(mx1, fmaxf(sacc[nt][2], sacc[nt][3]));
    }
    mx0 = fmaxf(mx0, __shfl_xor_sync(~0u, mx0, 1));
    mx0 = fmaxf(mx0, __shfl_xor_sync(~0u, mx0, 2));
    mx1 = fmaxf(mx1, __shfl_xor_sync(~0u, mx1, 1));
    mx1 = fmaxf(mx1, __shfl_xor_sync(~0u, mx1, 2));
    float nm0 = fmaxf(m0, mx0), nm1 = fmaxf(m1, mx1);
    float al0 = __expf(m0 - nm0), al1 = __expf(m1 - nm1);
    float s0 = 0.f, s1 = 0.f;
    __half* Pw = Ps + warp*(16*SP);
    #pragma unroll
    for (int nt = 0; nt < 8; nt++){
      float p0 = __expf(sacc[nt][0] - nm0), p1 = __expf(sacc[nt][1] - nm0);
      float p2 = __expf(sacc[nt][2] - nm1), p3 = __expf(sacc[nt][3] - nm1);
      s0 += p0 + p1; s1 += p2 + p3;
      __half* pp = Pw + g*SP + nt*8 + tg*2;
      *(__half2*)(pp)          = __floats2half2_rn(p0, p1);
      *(__half2*)(pp + 8*SP)   = __floats2half2_rn(p2, p3);
    }
    s0 += __shfl_xor_sync(~0u, s0, 1); s0 += __shfl_xor_sync(~0u, s0, 2);
    s1 += __shfl_xor_sync(~0u, s1, 1); s1 += __shfl_xor_sync(~0u, s1, 2);
    l0 = l0*al0 + s0; l1 = l1*al1 + s1;
    m0 = nm0; m1 = nm1;
    #pragma unroll
    for (int nt = 0; nt < 16; nt++){
      o[nt][0] *= al0; o[nt][1] *= al0; o[nt][2] *= al1; o[nt][3] *= al1;
    }
    __syncwarp();

    #pragma unroll
    for (int kk = 0; kk < 4; kk++){
      uint32_t af[4];
      const __half* ap = Pw + g*SP + kk*16 + tg*2;
      af[0] = *(const uint32_t*)(ap);
      af[1] = *(const uint32_t*)(ap + 8*SP);
      af[2] = *(const uint32_t*)(ap + 8);
      af[3] = *(const uint32_t*)(ap + 8*SP + 8);
      #pragma unroll
      for (int nt = 0; nt < 16; nt++){
        uint32_t bf[2];
        const __half* vp = Vtb + (nt*8 + g)*SV + kk*16 + tg*2;
        bf[0] = *(const uint32_t*)(vp);
        bf[1] = *(const uint32_t*)(vp + 8);
        mma16(o[nt], af, bf);
      }
    }
    __syncwarp();
  }

  float i0 = 1.0f / l0, i1 = 1.0f / l1;
  int t0 = qr0 + g;
  __half* ob0 = outp + (size_t)(b*TLEN + t0)*DIM + h*HD;
  __half* ob1 = outp + (size_t)(b*TLEN + t0 + 8)*DIM + h*HD;
  #pragma unroll
  for (int nt = 0; nt < 16; nt++){
    int c = nt*8 + tg*2;
    *(__half2*)(ob0 + c) = __floats2half2_rn(o[nt][0]*i0, o[nt][1]*i0);
    *(__half2*)(ob1 + c) = __floats2half2_rn(o[nt][2]*i1, o[nt][3]*i1);
  }
}

// ---------------- driver ----------------
extern "C" void kernel_launch(void* const* d_in, const int* in_sizes, int n_in,
                              void* d_out, int out_size) {
  (void)in_sizes; (void)n_in; (void)out_size;
  const float* x       = (const float*)d_in[0];
  const float* qkv_w   = (const float*)d_in[1];
  const float* o_w     = (const float*)d_in[2];
  const float* o_scale = (const float*)d_in[3];
  const float* w1      = (const float*)d_in[4];
  const float* w2      = (const float*)d_in[5];
  const float* mscale  = (const float*)d_in[6];
  float* out   = (float*)d_out;
  float* out_x = out;
  float* out_k = out + (size_t)ROWS*DIM;
  float* out_v = out + 2*(size_t)ROWS*DIM;

  float *qkvb; __half *xnh, *attnh, *hh, *wqkvh, *owh, *w1h, *w2h; float2* trig;
  cudaGetSymbolAddress((void**)&qkvb,  g_qkv);
  cudaGetSymbolAddress((void**)&xnh,   g_xnh);
  cudaGetSymbolAddress((void**)&attnh, g_attnh);
  cudaGetSymbolAddress((void**)&hh,    g_hh);
  cudaGetSymbolAddress((void**)&wqkvh, g_wqkvh);
  cudaGetSymbolAddress((void**)&owh,   g_owh);
  cudaGetSymbolAddress((void**)&w1h,   g_w1h);
  cudaGetSymbolAddress((void**)&w2h,   g_w2h);
  cudaGetSymbolAddress((void**)&trig,  g_trig);

  const int GEMM_SMEM = 3*(128 + 256)*72*2;         // 165888 bytes
  const int ATTN_SMEM = (128*136 + 2*64*136 + 2*128*72 + 8*16*72) * 2;  // 124928 bytes
  cudaFuncSetAttribute(hgemm<0>, cudaFuncAttributeMaxDynamicSharedMemorySize, GEMM_SMEM);
  cudaFuncSetAttribute(hgemm<1>, cudaFuncAttributeMaxDynamicSharedMemorySize, GEMM_SMEM);
  cudaFuncSetAttribute(hgemm<2>, cudaFuncAttributeMaxDynamicSharedMemorySize, GEMM_SMEM);
  cudaFuncSetAttribute(attn_k,   cudaFuncAttributeMaxDynamicSharedMemorySize, ATTN_SMEM);

  // 0. trig table + weight conversions fp32 -> fp16
  trig_k<<<TLEN*32/256, 256>>>(trig);
  f2h_k<<<(3*DIM*DIM/4 + 255)/256, 256>>>((const float4*)qkv_w, (__half2*)wqkvh, 3*DIM*DIM/4);
  f2h_k<<<(DIM*DIM/4   + 255)/256, 256>>>((const float4*)o_w,   (__half2*)owh,   DIM*DIM/4);
  f2h_k<<<(4*DIM*DIM/4 + 255)/256, 256>>>((const float4*)w1,    (__half2*)w1h,   4*DIM*DIM/4);
  f2h_k<<<(4*DIM*DIM/4 + 255)/256, 256>>>((const float4*)w2,    (__half2*)w2h,   4*DIM*DIM/4);

  // 1. rmsnorm(x) -> xnh (half)
  rmsnorm_k<<<ROWS, 256>>>(x, xnh);
  // 2. qkv = xnh @ wqkvh^T  -> fp32  [8192 x 6144]
  hgemm<0><<<dim3(6144/256, ROWS/128), 256, GEMM_SMEM>>>(xnh, wqkvh, qkvb, ROWS, 3*DIM, DIM, nullptr, nullptr);
  // 3. QK-norm + rotary (table), emit k,v outputs
  qkrot_k<<<ROWS, 256>>>(qkvb, trig, out_k, out_v);
  // 4. causal attention -> attnh (half)
  attn_k<<<dim3(TLEN/128, NB*NH), 256, ATTN_SMEM>>>(qkvb, attnh);
  // 5. x1 = x + (attnh @ owh^T) * o_scale  -> out_x (fp32)
  hgemm<1><<<dim3(DIM/256, ROWS/128), 256, GEMM_SMEM>>>(attnh, owh, out_x, ROWS, DIM, DIM, x, o_scale);
  // 6. rmsnorm(x1) -> xnh
  rmsnorm_k<<<ROWS, 256>>>(out_x, xnh);
  // 7. h = rn(relu(xnh @ w1h^T)^2)  -> hh (half)  [8192 x 8192]
  hgemm<2><<<dim3(4*DIM/256, ROWS/128), 256, GEMM_SMEM>>>(xnh, w1h, hh, ROWS, 4*DIM, DIM, nullptr, nullptr);
  // 8. x_out = x1 + (hh @ w2h^T) * mlp_scale  -> out_x (in place)
  hgemm<1><<<dim3(DIM/256, ROWS/128), 256, GEMM_SMEM>>>(hh, w2h, out_x, ROWS, DIM, 4*DIM, out_x, mscale);
}

// round 14
// speedup vs baseline: 1.5226x; 1.5226x over previous
#include <cuda_runtime.h>
#include <cuda_fp16.h>
#include <cstdint>
#include <math.h>

#define DIM 2048
#define TLEN 2048
#define NB 4
#define HD 128
#define NH 16
#define ROWS (NB*TLEN)   // 8192

// ---------------- scratch (device globals; no allocations allowed) ----------------
__device__ float  g_qkv[(size_t)ROWS*3*DIM];       // fp32 qkv (attn + qkrot path)
__device__ __half g_xnh[(size_t)ROWS*DIM];         // normalized activations (half)
__device__ __half g_attnh[(size_t)ROWS*DIM];       // attention output (half)
__device__ __half g_hh[(size_t)ROWS*4*DIM];        // mlp hidden (half)
__device__ __half g_wqkvh[(size_t)3*DIM*DIM];      // half weights
__device__ __half g_owh[(size_t)DIM*DIM];
__device__ __half g_w1h[(size_t)4*DIM*DIM];
__device__ __half g_w2h[(size_t)4*DIM*DIM];
__device__ float2 g_trig[(size_t)TLEN*32];         // (cos,sin) per (t, freq-lane)

// ---------------- helpers ----------------
__device__ __forceinline__ void cp16h(__half* s, const __half* g){
  uint32_t sa = (uint32_t)__cvta_generic_to_shared(s);
  asm volatile("cp.async.cg.shared.global [%0], [%1], 16;\n" :: "r"(sa), "l"(g));
}
__device__ __forceinline__ void cp_commit(){ asm volatile("cp.async.commit_group;\n" ::: "memory"); }
template<int N> __device__ __forceinline__ void cp_wait(){
  asm volatile("cp.async.wait_group %0;\n" :: "n"(N) : "memory");
}

// fp16 mma: D(16x8,f32) += A(16x16,f16,row) * B(16x8,f16,col)
__device__ __forceinline__ void mma16(float* d, const uint32_t* a, const uint32_t* b){
  asm volatile(
    "mma.sync.aligned.m16n8k16.row.col.f32.f16.f16.f32 "
    "{%0,%1,%2,%3}, {%4,%5,%6,%7}, {%8,%9}, {%0,%1,%2,%3};\n"
    : "+f"(d[0]), "+f"(d[1]), "+f"(d[2]), "+f"(d[3])
    : "r"(a[0]), "r"(a[1]), "r"(a[2]), "r"(a[3]), "r"(b[0]), "r"(b[1]));
}

__device__ __forceinline__ void ldsm4(uint32_t* r, uint32_t addr){
  asm volatile("ldmatrix.sync.aligned.m8n8.x4.shared.b16 {%0,%1,%2,%3}, [%4];"
    : "=r"(r[0]), "=r"(r[1]), "=r"(r[2]), "=r"(r[3]) : "r"(addr));
}

// ---------------- rotary trig table (computed once; same bits as before) ----------------
__global__ void __launch_bounds__(256) trig_k(float2* __restrict__ tb){
  int i = blockIdx.x * 256 + threadIdx.x;       // 65536 entries
  int t = i >> 5, l = i & 31;
  double fd = pow(1.0e-4, (double)l * (1.0/31.0));
  float thf = (float)t * (float)fd;
  tb[i] = make_float2((float)cos((double)thf), (float)sin((double)thf));
}

// ---------------- fp32 -> fp16 bulk convert ----------------
__global__ void __launch_bounds__(256) f2h_k(const float4* __restrict__ in,
                                             __half2* __restrict__ out, int n4){
  int i = blockIdx.x * 256 + threadIdx.x;
  if (i < n4){
    float4 v = in[i];
    out[2*i]   = __floats2half2_rn(v.x, v.y);
    out[2*i+1] = __floats2half2_rn(v.z, v.w);
  }
}

// ---------------- RMSNorm over last dim (2048), half output ----------------
__global__ void __launch_bounds__(256) rmsnorm_k(const float* __restrict__ x, __half* __restrict__ o){
  __shared__ float red[256];
  size_t base = (size_t)blockIdx.x * DIM;
  const float4* xv = (const float4*)(x + base);
  __half2* ov = (__half2*)(o + base);
  int tid = threadIdx.x;
  float4 a = xv[tid], b = xv[tid + 256];
  float ss = a.x*a.x + a.y*a.y + a.z*a.z + a.w*a.w
           + b.x*b.x + b.y*b.y + b.z*b.z + b.w*b.w;
  red[tid] = ss;
  __syncthreads();
  #pragma unroll
  for (int s = 128; s > 0; s >>= 1){
    if (tid < s) red[tid] += red[tid + s];
    __syncthreads();
  }
  float sc = 1.0f / sqrtf(red[0] * (1.0f/DIM) + 1e-6f);
  ov[2*tid]       = __floats2half2_rn(a.x*sc, a.y*sc);
  ov[2*tid+1]     = __floats2half2_rn(a.z*sc, a.w*sc);
  ov[2*(tid+256)]   = __floats2half2_rn(b.x*sc, b.y*sc);
  ov[2*(tid+256)+1] = __floats2half2_rn(b.z*sc, b.w*sc);
}

// ---------------- QK head-norm + rotary (table-driven) + emit k,v outputs ----------------
__global__ void __launch_bounds__(256) qkrot_k(float* __restrict__ qkv,
                                               const float2* __restrict__ trig,
                                               float* __restrict__ out_k,
                                               float* __restrict__ out_v){
  int row = blockIdx.x;
  int t = row & (TLEN - 1);
  int tid = threadIdx.x, w = tid >> 5, l = tid & 31;

  float2 cssn = trig[(t << 5) | l];
  float cs = cssn.x, sn = cssn.y;

  float* base = qkv + (size_t)row * (3*DIM);
  for (int hh = w; hh < 32; hh += 8){
    int isk = (hh >= 16);
    int h = hh & 15;
    float* p = base + (isk ? DIM : 0) + h*HD;
    float x0 = p[l], x1 = p[l+32], x2 = p[l+64], x3 = p[l+96];
    float ss = x0*x0 + x1*x1 + x2*x2 + x3*x3;
    #pragma unroll
    for (int o = 16; o; o >>= 1) ss += __shfl_xor_sync(~0u, ss, o);
    float sc = 1.0f / sqrtf(ss * (1.0f/HD) + 1e-6f);
    x0 *= sc; x1 *= sc; x2 *= sc; x3 *= sc;
    float y0 =  x0*cs + x2*sn;
    float y2 = -x0*sn + x2*cs;
    p[l] = y0; p[l+32] = x1; p[l+64] = y2; p[l+96] = x3;
    if (isk){
      float* ok = out_k + (size_t)row*DIM + h*HD;
      ok[l] = y0; ok[l+32] = x1; ok[l+64] = y2; ok[l+96] = x3;
    }
  }
  const float* vsrc = base + 2*DIM;
  float* vo = out_v + (size_t)row*DIM;
  for (int i = tid; i < DIM; i += 256) vo[i] = vsrc[i];
}

// ---------------- fp16 GEMM: C[M,N] = A[M,K] @ B[N,K]^T ----------------
// CTA tile 128x256, 8 warps 2x4, warp tile 64x64. K-stage 64, 3-buffer cp.async ring,
// lookahead 2, ONE __syncthreads per stage, ldmatrix fragment loads.
// EPI 0: plain fp32 store. EPI 1: fp32 C = res + acc*svec[col]. EPI 2: half C = rn(relu(acc)^2)
template<int EPI>
__global__ void __launch_bounds__(256, 1) hgemm(
    const __half* __restrict__ A, const __half* __restrict__ B, void* __restrict__ Cv,
    int M, int N, int K, const float* __restrict__ res, const float* __restrict__ svec)
{
  extern __shared__ __half smh[];
  const int SH = 72;                        // half stride: 8 rows span all 32 banks
  __half* As = smh;                         // [3][128][72]
  __half* Bs = smh + 3*128*SH;              // [3][256][72]
  int tid = threadIdx.x;
  int warp = tid >> 5, lane = tid & 31;
  int wm = (warp >> 2) * 64, wn = (warp & 3) * 64;
  int g = lane >> 2, tg = lane & 3;
  int bm = blockIdx.y * 128, bn = blockIdx.x * 256;
  const __half* gA = A + (size_t)bm * K;
  const __half* gB = B + (size_t)bn * K;
  int lrow = tid >> 3, lseg = (tid & 7) * 8;

  // ldmatrix per-lane address components
  uint32_t sA = (uint32_t)__cvta_generic_to_shared(As);
  uint32_t sB = sA + 3*128*SH*2;
  uint32_t a_row  = (lane & 7) + ((lane >> 3) & 1) * 8;
  uint32_t a_koff = (lane >> 4) * 8;
  uint32_t b_row  = (lane & 7) + (lane >> 4) * 8;
  uint32_t b_koff = ((lane >> 3) & 1) * 8;
  uint32_t awo = (uint32_t)(wm + a_row) * (SH*2) + a_koff*2;
  uint32_t bwo = (uint32_t)(wn + b_row) * (SH*2) + b_koff*2;

  float acc[4][8][4];
  #pragma unroll
  for (int i = 0; i < 4; i++)
    #pragma unroll
    for (int j = 0; j < 8; j++)
      #pragma unroll
      for (int q = 0; q < 4; q++) acc[i][j][q] = 0.f;

  auto load_stage = [&](int s, int buf){
    int k0 = s * 64;
    __half* as = As + buf * (128*SH);
    __half* bs = Bs + buf * (256*SH);
    #pragma unroll
    for (int i = 0; i < 4; i++){
      int r = lrow + i*32;
      cp16h(as + r*SH + lseg, gA + (size_t)r*K + k0 + lseg);
    }
    #pragma unroll
    for (int i = 0; i < 8; i++){
      int r = lrow + i*32;
      cp16h(bs + r*SH + lseg, gB + (size_t)r*K + k0 + lseg);
    }
  };

  int S = K / 64;
  load_stage(0, 0); cp_commit();
  load_stage(1, 1); cp_commit();

  int buf = 0, nb = 2;
  for (int s = 0; s < S; s++){
    if (s + 1 < S) cp_wait<1>(); else cp_wait<0>();
    __syncthreads();                       // stage s resident; compute(s-1) retired by all warps
    if (s + 2 < S){                        // load into buffer (s+2)%3 == (s-1)%3 (now free)
      load_stage(s + 2, nb);
      cp_commit();
    }
    uint32_t aw = sA + (uint32_t)buf*(128*SH*2) + awo;
    uint32_t bw = sB + (uint32_t)buf*(256*SH*2) + bwo;
    #pragma unroll
    for (int kk = 0; kk < 4; kk++){
      uint32_t af[4][4], bf[8][2];
      #pragma unroll
      for (int mt = 0; mt < 4; mt++)
        ldsm4(af[mt], aw + (uint32_t)mt*(16*SH*2) + kk*32);
      #pragma unroll
      for (int p = 0; p < 4; p++){
        uint32_t r[4];
        ldsm4(r, bw + (uint32_t)p*(16*SH*2) + kk*32);
        bf[2*p][0]   = r[0]; bf[2*p][1]   = r[1];
        bf[2*p+1][0] = r[2]; bf[2*p+1][1] = r[3];
      }
      #pragma unroll
      for (int mt = 0; mt < 4; mt++)
        #pragma unroll
        for (int nt = 0; nt < 8; nt++)
          mma16(acc[mt][nt], af[mt], bf[nt]);
    }
    buf = (buf + 1) % 3;
    nb  = (nb + 1) % 3;
  }

  // epilogue
  #pragma unroll
  for (int mt = 0; mt < 4; mt++){
    int r0 = bm + wm + mt*16 + g;
    #pragma unroll
    for (int nt = 0; nt < 8; nt++){
      int c0 = bn + wn + nt*8 + tg*2;
      float a0 = acc[mt][nt][0], a1 = acc[mt][nt][1];
      float a2 = acc[mt][nt][2], a3 = acc[mt][nt][3];
      if (EPI == 0){
        float* C = (float*)Cv;
        *(float2*)(C + (size_t)r0*N + c0)     = make_float2(a0, a1);
        *(float2*)(C + (size_t)(r0+8)*N + c0) = make_float2(a2, a3);
      } else if (EPI == 1){
        float* C = (float*)Cv;
        float s0 = svec[c0], s1 = svec[c0+1];
        const float* rr0 = res + (size_t)r0*N + c0;
        const float* rr1 = res + (size_t)(r0+8)*N + c0;
        *(float2*)(C + (size_t)r0*N + c0)     = make_float2(rr0[0] + a0*s0, rr0[1] + a1*s1);
        *(float2*)(C + (size_t)(r0+8)*N + c0) = make_float2(rr1[0] + a2*s0, rr1[1] + a3*s1);
      } else {
        __half* C = (__half*)Cv;
        float v0 = fmaxf(a0, 0.f), v1 = fmaxf(a1, 0.f);
        float v2 = fmaxf(a2, 0.f), v3 = fmaxf(a3, 0.f);
        *(__half2*)(C + (size_t)r0*N + c0)     = __floats2half2_rn(v0*v0, v1*v1);
        *(__half2*)(C + (size_t)(r0+8)*N + c0) = __floats2half2_rn(v2*v2, v3*v3);
      }
    }
  }
}

// ---------------- causal flash attention (fp16 mma), Qtile=128, Ktile=64 ----------------
// Register-prefetch + double-buffered K/V smem tiles; ONE __syncthreads per kt.
// smem (halves): Qs 128x136, Ks[2] 64x136, Vt[2] 128x72, Ps 8 warps x 16x72
__global__ void __launch_bounds__(256) attn_k(const float* __restrict__ qkv, __half* __restrict__ outp)
{
  extern __shared__ __half smah[];
  const int SQ = 136, SV = 72, SP = 72;
  __half* Qs = smah;                        // 128*136
  __half* Ks = Qs + 128*SQ;                 // 2 x 64*136
  __half* Vt = Ks + 2*64*SQ;                // 2 x 128*72  [d][key]
  __half* Ps = Vt + 2*128*SV;               // 8*16*72
  int tid = threadIdx.x, warp = tid >> 5, lane = tid & 31;
  int g = lane >> 2, tg = lane & 3;
  int qt = blockIdx.x;
  int bh = blockIdx.y; int b = bh >> 4, h = bh & 15;
  const size_t rs = 3*DIM;

  const float* qbase = qkv + (size_t)(b*TLEN + qt*128)*rs + h*HD;
  for (int i = tid; i < 128*32; i += 256){
    int r = i >> 5, c4 = (i & 31) * 4;
    float4 v = *(const float4*)(qbase + (size_t)r*rs + c4);
    *(__half2*)(Qs + r*SQ + c4)     = __floats2half2_rn(v.x, v.y);
    *(__half2*)(Qs + r*SQ + c4 + 2) = __floats2half2_rn(v.z, v.w);
  }

  float o[16][4];
  #pragma unroll
  for (int i = 0; i < 16; i++){ o[i][0]=0.f; o[i][1]=0.f; o[i][2]=0.f; o[i][3]=0.f; }
  float m0 = -1e30f, m1 = -1e30f, l0 = 0.f, l1 = 0.f;
  int ktn = 2*qt + 2;
  int qr0 = qt*128 + warp*16;
  const float SCL = 0.08838834764831845f;

  // register prefetch staging
  float4 kreg[8];
  float4 vreg[4][2];
  auto load_tile = [&](int kt){
    const float* kb = qkv + (size_t)(b*TLEN + kt*64)*rs + DIM + h*HD;
    const float* vb = kb + DIM;
    #pragma unroll
    for (int u = 0; u < 8; u++){
      int i = tid + u*256;
      int r = i >> 5, c4 = (i & 31) * 4;
      kreg[u] = *(const float4*)(kb + (size_t)r*rs + c4);
    }
    #pragma unroll
    for (int u = 0; u < 4; u++){
      int i = tid + u*256;
      int p = i >> 5, ln = i & 31;
      int r0 = 2*p, c4 = ln*4;
      vreg[u][0] = *(const float4*)(vb + (size_t)r0*rs + c4);
      vreg[u][1] = *(const float4*)(vb + (size_t)(r0+1)*rs + c4);
    }
  };
  auto store_tile = [&](int bi){
    __half* Ksb = Ks + bi*(64*SQ);
    __half* Vtb = Vt + bi*(128*SV);
    #pragma unroll
    for (int u = 0; u < 8; u++){
      int i = tid + u*256;
      int r = i >> 5, c4 = (i & 31) * 4;
      *(__half2*)(Ksb + r*SQ + c4)     = __floats2half2_rn(kreg[u].x, kreg[u].y);
      *(__half2*)(Ksb + r*SQ + c4 + 2) = __floats2half2_rn(kreg[u].z, kreg[u].w);
    }
    #pragma unroll
    for (int u = 0; u < 4; u++){
      int i = tid + u*256;
      int p = i >> 5, ln = i & 31;
      int r0 = 2*p, c4 = ln*4;
      float a0[4] = {vreg[u][0].x, vreg[u][0].y, vreg[u][0].z, vreg[u][0].w};
      float a1[4] = {vreg[u][1].x, vreg[u][1].y, vreg[u][1].z, vreg[u][1].w};
      #pragma unroll
      for (int j = 0; j < 4; j++){
        int jj = (j + ln) & 3;
        *(__half2*)(Vtb + (c4 + jj)*SV + r0) = __floats2half2_rn(a0[jj], a1[jj]);
      }
    }
  };

  load_tile(0);
  for (int kt = 0; kt < ktn; kt++){
    int bi = kt & 1;
    // Race-safety: buf bi was last READ by compute(kt-2), which every warp finished
    // before arriving at iteration (kt-1)'s __syncthreads. Compute(kt-1) (possibly
    // in flight on other warps) reads buf bi^1 — disjoint. Single sync per iter.
    store_tile(bi);
    __syncthreads();
    if (kt + 1 < ktn) load_tile(kt + 1);   // overlap gmem latency with compute below
    if (kt*64 > qr0 + 15) continue;

    const __half* Ksb = Ks + bi*(64*SQ);
    const __half* Vtb = Vt + bi*(128*SV);

    float sacc[8][4];
    #pragma unroll
    for (int nt = 0; nt < 8; nt++){ sacc[nt][0]=0.f; sacc[nt][1]=0.f; sacc[nt][2]=0.f; sacc[nt][3]=0.f; }
    #pragma unroll
    for (int kk = 0; kk < 8; kk++){
      uint32_t af[4];
      const __half* qp = Qs + (warp*16 + g)*SQ + kk*16 + tg*2;
      af[0] = *(const uint32_t*)(qp);
      af[1] = *(const uint32_t*)(qp + 8*SQ);
      af[2] = *(const uint32_t*)(qp + 8);
      af[3] = *(const uint32_t*)(qp + 8*SQ + 8);
      #pragma unroll
      for (int nt = 0; nt < 8; nt++){
        uint32_t bf[2];
        const __half* kp = Ksb + (nt*8 + g)*SQ + kk*16 + tg*2;
        bf[0] = *(const uint32_t*)(kp);
        bf[1] = *(const uint32_t*)(kp + 8);
        mma16(sacc[nt], af, bf);
      }
    }

    int q0 = qr0 + g, q1 = q0 + 8;
    float mx0 = -1e30f, mx1 = -1e30f;
    #pragma unroll
    for (int nt = 0; nt < 8; nt++){
      int c = kt*64 + nt*8 + tg*2;
      sacc[nt][0] = (c     <= q0) ? sacc[nt][0]*SCL : -1e30f;
      sacc[nt][1] = (c + 1 <= q0) ? sacc[nt][1]*SCL : -1e30f;
      sacc[nt][2] = (c     <= q1) ? sacc[nt][2]*SCL : -1e30f;
      sacc[nt][3] = (c + 1 <= q1) ? sacc[nt][3]*SCL : -1e30f;
      mx0 = fmaxf(mx0, fmaxf(sacc[nt][0], sacc[nt][1]));
      mx1 = fmaxf(mx1, fmaxf(sacc[nt][2], sacc[nt][3]));
    }
    mx0 = fmaxf(mx0, __shfl_xor_sync(~0u, mx0, 1));
    mx0 = fmaxf(mx0, __shfl_xor_sync(~0u, mx0, 2));
    mx1 = fmaxf(mx1, __shfl_xor_sync(~0u, mx1, 1));
    mx1 = fmaxf(mx1, __shfl_xor_sync(~0u, mx1, 2));
    float nm0 = fmaxf(m0, mx0), nm1 = fmaxf(m1, mx1);
    float al0 = __expf(m0 - nm0), al1 = __expf(m1 - nm1);
    float s0 = 0.f, s1 = 0.f;
    __half* Pw = Ps + warp*(16*SP);
    #pragma unroll
    for (int nt = 0; nt < 8; nt++){
      float p0 = __expf(sacc[nt][0] - nm0), p1 = __expf(sacc[nt][1] - nm0);
      float p2 = __expf(sacc[nt][2] - nm1), p3 = __expf(sacc[nt][3] - nm1);
      s0 += p0 + p1; s1 += p2 + p3;
      __half* pp = Pw + g*SP + nt*8 + tg*2;
      *(__half2*)(pp)          = __floats2half2_rn(p0, p1);
      *(__half2*)(pp + 8*SP)   = __floats2half2_rn(p2, p3);
    }
    s0 += __shfl_xor_sync(~0u, s0, 1); s0 += __shfl_xor_sync(~0u, s0, 2);
    s1 += __shfl_xor_sync(~0u, s1, 1); s1 += __shfl_xor_sync(~0u, s1, 2);
    l0 = l0*al0 + s0; l1 = l1*al1 + s1;
    m0 = nm0; m1 = nm1;
    #pragma unroll
    for (int nt = 0; nt < 16; nt++){
      o[nt][0] *= al0; o[nt][1] *= al0; o[nt][2] *= al1; o[nt][3] *= al1;
    }
    __syncwarp();

    #pragma unroll
    for (int kk = 0; kk < 4; kk++){
      uint32_t af[4];
      const __half* ap = Pw + g*SP + kk*16 + tg*2;
      af[0] = *(const uint32_t*)(ap);
      af[1] = *(const uint32_t*)(ap + 8*SP);
      af[2] = *(const uint32_t*)(ap + 8);
      af[3] = *(const uint32_t*)(ap + 8*SP + 8);
      #pragma unroll
      for (int nt = 0; nt < 16; nt++){
        uint32_t bf[2];
        const __half* vp = Vtb + (nt*8 + g)*SV + kk*16 + tg*2;
        bf[0] = *(const uint32_t*)(vp);
        bf[1] = *(const uint32_t*)(vp + 8);
        mma16(o[nt], af, bf);
      }
    }
    __syncwarp();
  }

  float i0 = 1.0f / l0, i1 = 1.0f / l1;
  int t0 = qr0 + g;
  __half* ob0 = outp + (size_t)(b*TLEN + t0)*DIM + h*HD;
  __half* ob1 = outp + (size_t)(b*TLEN + t0 + 8)*DIM + h*HD;
  #pragma unroll
  for (int nt = 0; nt < 16; nt++){
    int c = nt*8 + tg*2;
    *(__half2*)(ob0 + c) = __floats2half2_rn(o[nt][0]*i0, o[nt][1]*i0);
    *(__half2*)(ob1 + c) = __floats2half2_rn(o[nt][2]*i1, o[nt][3]*i1);
  }
}

// ---------------- driver ----------------
extern "C" void kernel_launch(void* const* d_in, const int* in_sizes, int n_in,
                              void* d_out, int out_size) {
  (void)in_sizes; (void)n_in; (void)out_size;
  const float* x       = (const float*)d_in[0];
  const float* qkv_w   = (const float*)d_in[1];
  const float* o_w     = (const float*)d_in[2];
  const float* o_scale = (const float*)d_in[3];
  const float* w1      = (const float*)d_in[4];
  const float* w2      = (const float*)d_in[5];
  const float* mscale  = (const float*)d_in[6];
  float* out   = (float*)d_out;
  float* out_x = out;
  float* out_k = out + (size_t)ROWS*DIM;
  float* out_v = out + 2*(size_t)ROWS*DIM;

  float *qkvb; __half *xnh, *attnh, *hh, *wqkvh, *owh, *w1h, *w2h; float2* trig;
  cudaGetSymbolAddress((void**)&qkvb,  g_qkv);
  cudaGetSymbolAddress((void**)&xnh,   g_xnh);
  cudaGetSymbolAddress((void**)&attnh, g_attnh);
  cudaGetSymbolAddress((void**)&hh,    g_hh);
  cudaGetSymbolAddress((void**)&wqkvh, g_wqkvh);
  cudaGetSymbolAddress((void**)&owh,   g_owh);
  cudaGetSymbolAddress((void**)&w1h,   g_w1h);
  cudaGetSymbolAddress((void**)&w2h,   g_w2h);
  cudaGetSymbolAddress((void**)&trig,  g_trig);

  const int GEMM_SMEM = 3*(128 + 256)*72*2;         // 165888 bytes
  const int ATTN_SMEM = (128*136 + 2*64*136 + 2*128*72 + 8*16*72) * 2;  // 124928 bytes
  cudaFuncSetAttribute(hgemm<0>, cudaFuncAttributeMaxDynamicSharedMemorySize, GEMM_SMEM);
  cudaFuncSetAttribute(hgemm<1>, cudaFuncAttributeMaxDynamicSharedMemorySize, GEMM_SMEM);
  cudaFuncSetAttribute(hgemm<2>, cudaFuncAttributeMaxDynamicSharedMemorySize, GEMM_SMEM);
  cudaFuncSetAttribute(attn_k,   cudaFuncAttributeMaxDynamicSharedMemorySize, ATTN_SMEM);

  // 0. trig table + weight conversions fp32 -> fp16
  trig_k<<<TLEN*32/256, 256>>>(trig);
  f2h_k<<<(3*DIM*DIM/4 + 255)/256, 256>>>((const float4*)qkv_w, (__half2*)wqkvh, 3*DIM*DIM/4);
  f2h_k<<<(DIM*DIM/4   + 255)/256, 256>>>((const float4*)o_w,   (__half2*)owh,   DIM*DIM/4);
  f2h_k<<<(4*DIM*DIM/4 + 255)/256, 256>>>((const float4*)w1,    (__half2*)w1h,   4*DIM*DIM/4);
  f2h_k<<<(4*DIM*DIM/4 + 255)/256, 256>>>((const float4*)w2,    (__half2*)w2h,   4*DIM*DIM/4);

  // 1. rmsnorm(x) -> xnh (half)
  rmsnorm_k<<<ROWS, 256>>>(x, xnh);
  // 2. qkv = xnh @ wqkvh^T  -> fp32  [8192 x 6144]
  hgemm<0><<<dim3(6144/256, ROWS/128), 256, GEMM_SMEM>>>(xnh, wqkvh, qkvb, ROWS, 3*DIM, DIM, nullptr, nullptr);
  // 3. QK-norm + rotary (table), emit k,v outputs
  qkrot_k<<<ROWS, 256>>>(qkvb, trig, out_k, out_v);
  // 4. causal attention -> attnh (half)
  attn_k<<<dim3(TLEN/128, NB*NH), 256, ATTN_SMEM>>>(qkvb, attnh);
  // 5. x1 = x + (attnh @ owh^T) * o_scale  -> out_x (fp32)
  hgemm<1><<<dim3(DIM/256, ROWS/128), 256, GEMM_SMEM>>>(attnh, owh, out_x, ROWS, DIM, DIM, x, o_scale);
  // 6. rmsnorm(x1) -> xnh
  rmsnorm_k<<<ROWS, 256>>>(out_x, xnh);
  // 7. h = rn(relu(xnh @ w1h^T)^2)  -> hh (half)  [8192 x 8192]
  hgemm<2><<<dim3(4*DIM/256, ROWS/128), 256, GEMM_SMEM>>>(xnh, w1h, hh, ROWS, 4*DIM, DIM, nullptr, nullptr);
  // 8. x_out = x1 + (hh @ w2h^T) * mlp_scale  -> out_x (in place)
  hgemm<1><<<dim3(DIM/256, ROWS/128), 256, GEMM_SMEM>>>(hh, w2h, out_x, ROWS, DIM, 4*DIM, out_x, mscale);
}

// round 16
// speedup vs baseline: 1.5477x; 1.0165x over previous
#include <cuda_runtime.h>
#include <cuda_fp16.h>
#include <cstdint>
#include <math.h>

#define DIM 2048
#define TLEN 2048
#define NB 4
#define HD 128
#define NH 16
#define ROWS (NB*TLEN)   // 8192

// ---------------- scratch (device globals; no allocations allowed) ----------------
__device__ float  g_qkv[(size_t)ROWS*2*DIM];       // fp32 q,k (q rotated in place; k raw)
__device__ __half g_xnh[(size_t)ROWS*DIM];         // normalized activations (half)
__device__ __half g_attnh[(size_t)ROWS*DIM];       // attention output (half)
__device__ __half g_hh[(size_t)ROWS*4*DIM];        // mlp hidden (half)
__device__ __half g_wqkvh[(size_t)3*DIM*DIM];      // half weights
__device__ __half g_owh[(size_t)DIM*DIM];
__device__ __half g_w1h[(size_t)4*DIM*DIM];
__device__ __half g_w2h[(size_t)4*DIM*DIM];
__device__ float2 g_trig[(size_t)TLEN*32];         // (cos,sin) per (t, freq-lane)

// ---------------- helpers ----------------
__device__ __forceinline__ void cp16h(__half* s, const __half* g){
  uint32_t sa = (uint32_t)__cvta_generic_to_shared(s);
  asm volatile("cp.async.cg.shared.global [%0], [%1], 16;\n" :: "r"(sa), "l"(g));
}
__device__ __forceinline__ void cp_commit(){ asm volatile("cp.async.commit_group;\n" ::: "memory"); }
template<int N> __device__ __forceinline__ void cp_wait(){
  asm volatile("cp.async.wait_group %0;\n" :: "n"(N) : "memory");
}

// fp16 mma: D(16x8,f32) += A(16x16,f16,row) * B(16x8,f16,col)
__device__ __forceinline__ void mma16(float* d, const uint32_t* a, const uint32_t* b){
  asm volatile(
    "mma.sync.aligned.m16n8k16.row.col.f32.f16.f16.f32 "
    "{%0,%1,%2,%3}, {%4,%5,%6,%7}, {%8,%9}, {%0,%1,%2,%3};\n"
    : "+f"(d[0]), "+f"(d[1]), "+f"(d[2]), "+f"(d[3])
    : "r"(a[0]), "r"(a[1]), "r"(a[2]), "r"(a[3]), "r"(b[0]), "r"(b[1]));
}

__device__ __forceinline__ void ldsm4(uint32_t* r, uint32_t addr){
  asm volatile("ldmatrix.sync.aligned.m8n8.x4.shared.b16 {%0,%1,%2,%3}, [%4];"
    : "=r"(r[0]), "=r"(r[1]), "=r"(r[2]), "=r"(r[3]) : "r"(addr));
}

// ---------------- rotary trig table (computed once; same bits as before) ----------------
__global__ void __launch_bounds__(256) trig_k(float2* __restrict__ tb){
  int i = blockIdx.x * 256 + threadIdx.x;       // 65536 entries
  int t = i >> 5, l = i & 31;
  double fd = pow(1.0e-4, (double)l * (1.0/31.0));
  float thf = (float)t * (float)fd;
  tb[i] = make_float2((float)cos((double)thf), (float)sin((double)thf));
}

// ---------------- fp32 -> fp16 bulk convert ----------------
__global__ void __launch_bounds__(256) f2h_k(const float4* __restrict__ in,
                                             __half2* __restrict__ out, int n4){
  int i = blockIdx.x * 256 + threadIdx.x;
  if (i < n4){
    float4 v = in[i];
    out[2*i]   = __floats2half2_rn(v.x, v.y);
    out[2*i+1] = __floats2half2_rn(v.z, v.w);
  }
}

// ---------------- RMSNorm over last dim (2048), half output ----------------
__global__ void __launch_bounds__(256) rmsnorm_k(const float* __restrict__ x, __half* __restrict__ o){
  __shared__ float red[256];
  size_t base = (size_t)blockIdx.x * DIM;
  const float4* xv = (const float4*)(x + base);
  __half2* ov = (__half2*)(o + base);
  int tid = threadIdx.x;
  float4 a = xv[tid], b = xv[tid + 256];
  float ss = a.x*a.x + a.y*a.y + a.z*a.z + a.w*a.w
           + b.x*b.x + b.y*b.y + b.z*b.z + b.w*b.w;
  red[tid] = ss;
  __syncthreads();
  #pragma unroll
  for (int s = 128; s > 0; s >>= 1){
    if (tid < s) red[tid] += red[tid + s];
    __syncthreads();
  }
  float sc = 1.0f / sqrtf(red[0] * (1.0f/DIM) + 1e-6f);
  ov[2*tid]       = __floats2half2_rn(a.x*sc, a.y*sc);
  ov[2*tid+1]     = __floats2half2_rn(a.z*sc, a.w*sc);
  ov[2*(tid+256)]   = __floats2half2_rn(b.x*sc, b.y*sc);
  ov[2*(tid+256)+1] = __floats2half2_rn(b.z*sc, b.w*sc);
}

// ---------------- QK head-norm + rotary: q in place (stride 2*DIM), k -> out_k only ----------------
__global__ void __launch_bounds__(256) qkrot_k(float* __restrict__ qkv,
                                               const float2* __restrict__ trig,
                                               float* __restrict__ out_k){
  int row = blockIdx.x;
  int t = row & (TLEN - 1);
  int tid = threadIdx.x, w = tid >> 5, l = tid & 31;

  float2 cssn = trig[(t << 5) | l];
  float cs = cssn.x, sn = cssn.y;

  float* base = qkv + (size_t)row * (2*DIM);
  for (int hh = w; hh < 32; hh += 8){
    int isk = (hh >= 16);
    int h = hh & 15;
    float* p = base + (isk ? DIM : 0) + h*HD;
    float x0 = p[l], x1 = p[l+32], x2 = p[l+64], x3 = p[l+96];
    float ss = x0*x0 + x1*x1 + x2*x2 + x3*x3;
    #pragma unroll
    for (int o = 16; o; o >>= 1) ss += __shfl_xor_sync(~0u, ss, o);
    float sc = 1.0f / sqrtf(ss * (1.0f/HD) + 1e-6f);
    x0 *= sc; x1 *= sc; x2 *= sc; x3 *= sc;
    float y0 =  x0*cs + x2*sn;
    float y2 = -x0*sn + x2*cs;
    if (isk){
      float* ok = out_k + (size_t)row*DIM + h*HD;
      ok[l] = y0; ok[l+32] = x1; ok[l+64] = y2; ok[l+96] = x3;
    } else {
      p[l] = y0; p[l+32] = x1; p[l+64] = y2; p[l+96] = x3;
    }
  }
}

// ---------------- fp16 GEMM: C[M,N] = A[M,K] @ B[N,K]^T ----------------
// CTA tile 128x256, 8 warps 2x4, warp tile 64x64. K-stage 64, 3-buffer cp.async ring,
// lookahead 2, ONE __syncthreads per stage, ldmatrix fragment loads.
// EPI 0: plain fp32 store. EPI 1: fp32 C = res + acc*svec[col]. EPI 2: half C = rn(relu(acc)^2)
template<int EPI>
__global__ void __launch_bounds__(256, 1) hgemm(
    const __half* __restrict__ A, const __half* __restrict__ B, void* __restrict__ Cv,
    int M, int N, int K, const float* __restrict__ res, const float* __restrict__ svec)
{
  extern __shared__ __half smh[];
  const int SH = 72;                        // half stride: 8 rows span all 32 banks
  __half* As = smh;                         // [3][128][72]
  __half* Bs = smh + 3*128*SH;              // [3][256][72]
  int tid = threadIdx.x;
  int warp = tid >> 5, lane = tid & 31;
  int wm = (warp >> 2) * 64, wn = (warp & 3) * 64;
  int g = lane >> 2, tg = lane & 3;
  int bm = blockIdx.y * 128, bn = blockIdx.x * 256;
  const __half* gA = A + (size_t)bm * K;
  const __half* gB = B + (size_t)bn * K;
  int lrow = tid >> 3, lseg = (tid & 7) * 8;

  // ldmatrix per-lane address components
  uint32_t sA = (uint32_t)__cvta_generic_to_shared(As);
  uint32_t sB = sA + 3*128*SH*2;
  uint32_t a_row  = (lane & 7) + ((lane >> 3) & 1) * 8;
  uint32_t a_koff = (lane >> 4) * 8;
  uint32_t b_row  = (lane & 7) + (lane >> 4) * 8;
  uint32_t b_koff = ((lane >> 3) & 1) * 8;
  uint32_t awo = (uint32_t)(wm + a_row) * (SH*2) + a_koff*2;
  uint32_t bwo = (uint32_t)(wn + b_row) * (SH*2) + b_koff*2;

  float acc[4][8][4];
  #pragma unroll
  for (int i = 0; i < 4; i++)
    #pragma unroll
    for (int j = 0; j < 8; j++)
      #pragma unroll
      for (int q = 0; q < 4; q++) acc[i][j][q] = 0.f;

  auto load_stage = [&](int s, int buf){
    int k0 = s * 64;
    __half* as = As + buf * (128*SH);
    __half* bs = Bs + buf * (256*SH);
    #pragma unroll
    for (int i = 0; i < 4; i++){
      int r = lrow + i*32;
      cp16h(as + r*SH + lseg, gA + (size_t)r*K + k0 + lseg);
    }
    #pragma unroll
    for (int i = 0; i < 8; i++){
      int r = lrow + i*32;
      cp16h(bs + r*SH + lseg, gB + (size_t)r*K + k0 + lseg);
    }
  };

  int S = K / 64;
  load_stage(0, 0); cp_commit();
  load_stage(1, 1); cp_commit();

  int buf = 0, nb = 2;
  for (int s = 0; s < S; s++){
    if (s + 1 < S) cp_wait<1>(); else cp_wait<0>();
    __syncthreads();                       // stage s resident; compute(s-1) retired by all warps
    if (s + 2 < S){                        // load into buffer (s+2)%3 == (s-1)%3 (now free)
      load_stage(s + 2, nb);
      cp_commit();
    }
    uint32_t aw = sA + (uint32_t)buf*(128*SH*2) + awo;
    uint32_t bw = sB + (uint32_t)buf*(256*SH*2) + bwo;
    #pragma unroll
    for (int kk = 0; kk < 4; kk++){
      uint32_t af[4][4], bf[8][2];
      #pragma unroll
      for (int mt = 0; mt < 4; mt++)
        ldsm4(af[mt], aw + (uint32_t)mt*(16*SH*2) + kk*32);
      #pragma unroll
      for (int p = 0; p < 4; p++){
        uint32_t r[4];
        ldsm4(r, bw + (uint32_t)p*(16*SH*2) + kk*32);
        bf[2*p][0]   = r[0]; bf[2*p][1]   = r[1];
        bf[2*p+1][0] = r[2]; bf[2*p+1][1] = r[3];
      }
      #pragma unroll
      for (int mt = 0; mt < 4; mt++)
        #pragma unroll
        for (int nt = 0; nt < 8; nt++)
          mma16(acc[mt][nt], af[mt], bf[nt]);
    }
    buf = (buf + 1) % 3;
    nb  = (nb + 1) % 3;
  }

  // epilogue
  #pragma unroll
  for (int mt = 0; mt < 4; mt++){
    int r0 = bm + wm + mt*16 + g;
    #pragma unroll
    for (int nt = 0; nt < 8; nt++){
      int c0 = bn + wn + nt*8 + tg*2;
      float a0 = acc[mt][nt][0], a1 = acc[mt][nt][1];
      float a2 = acc[mt][nt][2], a3 = acc[mt][nt][3];
      if (EPI == 0){
        float* C = (float*)Cv;
        *(float2*)(C + (size_t)r0*N + c0)     = make_float2(a0, a1);
        *(float2*)(C + (size_t)(r0+8)*N + c0) = make_float2(a2, a3);
      } else if (EPI == 1){
        float* C = (float*)Cv;
        float s0 = svec[c0], s1 = svec[c0+1];
        const float* rr0 = res + (size_t)r0*N + c0;
        const float* rr1 = res + (size_t)(r0+8)*N + c0;
        *(float2*)(C + (size_t)r0*N + c0)     = make_float2(rr0[0] + a0*s0, rr0[1] + a1*s1);
        *(float2*)(C + (size_t)(r0+8)*N + c0) = make_float2(rr1[0] + a2*s0, rr1[1] + a3*s1);
      } else {
        __half* C = (__half*)Cv;
        float v0 = fmaxf(a0, 0.f), v1 = fmaxf(a1, 0.f);
        float v2 = fmaxf(a2, 0.f), v3 = fmaxf(a3, 0.f);
        *(__half2*)(C + (size_t)r0*N + c0)     = __floats2half2_rn(v0*v0, v1*v1);
        *(__half2*)(C + (size_t)(r0+8)*N + c0) = __floats2half2_rn(v2*v2, v3*v3);
      }
    }
  }
}

// ---------------- causal flash attention (fp16 mma), Qtile=128, Ktile=64 ----------------
// q from g_qkv (stride 2*DIM), k from out_k (stride DIM), v from out_v (stride DIM).
// Register-prefetch + double-buffered K/V smem tiles; ONE __syncthreads per kt.
__global__ void __launch_bounds__(256) attn_k(const float* __restrict__ qkv,
                                              const float* __restrict__ kin,
                                              const float* __restrict__ vin,
                                              __half* __restrict__ outp)
{
  extern __shared__ __half smah[];
  const int SQ = 136, SV = 72, SP = 72;
  __half* Qs = smah;                        // 128*136
  __half* Ks = Qs + 128*SQ;                 // 2 x 64*136
  __half* Vt = Ks + 2*64*SQ;                // 2 x 128*72  [d][key]
  __half* Ps = Vt + 2*128*SV;               // 8*16*72
  int tid = threadIdx.x, warp = tid >> 5, lane = tid & 31;
  int g = lane >> 2, tg = lane & 3;
  int qt = blockIdx.x;
  int bh = blockIdx.y; int b = bh >> 4, h = bh & 15;
  const size_t rsq = 2*DIM;

  const float* qbase = qkv + (size_t)(b*TLEN + qt*128)*rsq + h*HD;
  for (int i = tid; i < 128*32; i += 256){
    int r = i >> 5, c4 = (i & 31) * 4;
    float4 v = *(const float4*)(qbase + (size_t)r*rsq + c4);
    *(__half2*)(Qs + r*SQ + c4)     = __floats2half2_rn(v.x, v.y);
    *(__half2*)(Qs + r*SQ + c4 + 2) = __floats2half2_rn(v.z, v.w);
  }

  float o[16][4];
  #pragma unroll
  for (int i = 0; i < 16; i++){ o[i][0]=0.f; o[i][1]=0.f; o[i][2]=0.f; o[i][3]=0.f; }
  float m0 = -1e30f, m1 = -1e30f, l0 = 0.f, l1 = 0.f;
  int ktn = 2*qt + 2;
  int qr0 = qt*128 + warp*16;
  const float SCL = 0.08838834764831845f;

  // register prefetch staging
  float4 kreg[8];
  float4 vreg[4][2];
  auto load_tile = [&](int kt){
    const float* kb = kin + (size_t)(b*TLEN + kt*64)*DIM + h*HD;
    const float* vb = vin + (size_t)(b*TLEN + kt*64)*DIM + h*HD;
    #pragma unroll
    for (int u = 0; u < 8; u++){
      int i = tid + u*256;
      int r = i >> 5, c4 = (i & 31) * 4;
      kreg[u] = *(const float4*)(kb + (size_t)r*DIM + c4);
    }
    #pragma unroll
    for (int u = 0; u < 4; u++){
      int i = tid + u*256;
      int p = i >> 5, ln = i & 31;
      int r0 = 2*p, c4 = ln*4;
      vreg[u][0] = *(const float4*)(vb + (size_t)r0*DIM + c4);
      vreg[u][1] = *(const float4*)(vb + (size_t)(r0+1)*DIM + c4);
    }
  };
  auto store_tile = [&](int bi){
    __half* Ksb = Ks + bi*(64*SQ);
    __half* Vtb = Vt + bi*(128*SV);
    #pragma unroll
    for (int u = 0; u < 8; u++){
      int i = tid + u*256;
      int r = i >> 5, c4 = (i & 31) * 4;
      *(__half2*)(Ksb + r*SQ + c4)     = __floats2half2_rn(kreg[u].x, kreg[u].y);
      *(__half2*)(Ksb + r*SQ + c4 + 2) = __floats2half2_rn(kreg[u].z, kreg[u].w);
    }
    #pragma unroll
    for (int u = 0; u < 4; u++){
      int i = tid + u*256;
      int p = i >> 5, ln = i & 31;
      int r0 = 2*p, c4 = ln*4;
      float a0[4] = {vreg[u][0].x, vreg[u][0].y, vreg[u][0].z, vreg[u][0].w};
      float a1[4] = {vreg[u][1].x, vreg[u][1].y, vreg[u][1].z, vreg[u][1].w};
      #pragma unroll
      for (int j = 0; j < 4; j++){
        int jj = (j + ln) & 3;
        *(__half2*)(Vtb + (c4 + jj)*SV + r0) = __floats2half2_rn(a0[jj], a1[jj]);
      }
    }
  };

  load_tile(0);
  for (int kt = 0; kt < ktn; kt++){
    int bi = kt & 1;
    // Race-safety: buf bi was last READ by compute(kt-2), which every warp finished
    // before arriving at iteration (kt-1)'s __syncthreads. Compute(kt-1) (possibly
    // in flight on other warps) reads buf bi^1 — disjoint. Single sync per iter.
    store_tile(bi);
    __syncthreads();
    if (kt + 1 < ktn) load_tile(kt + 1);   // overlap gmem latency with compute below
    if (kt*64 > qr0 + 15) continue;

    const __half* Ksb = Ks + bi*(64*SQ);
    const __half* Vtb = Vt + bi*(128*SV);

    float sacc[8][4];
    #pragma unroll
    for (int nt = 0; nt < 8; nt++){ sacc[nt][0]=0.f; sacc[nt][1]=0.f; sacc[nt][2]=0.f; sacc[nt][3]=0.f; }
    #pragma unroll
    for (int kk = 0; kk < 8; kk++){
      uint32_t af[4];
      const __half* qp = Qs + (warp*16 + g)*SQ + kk*16 + tg*2;
      af[0] = *(const uint32_t*)(qp);
      af[1] = *(const uint32_t*)(qp + 8*SQ);
      af[2] = *(const uint32_t*)(qp + 8);
      af[3] = *(const uint32_t*)(qp + 8*SQ + 8);
      #pragma unroll
      for (int nt = 0; nt < 8; nt++){
        uint32_t bf[2];
        const __half* kp = Ksb + (nt*8 + g)*SQ + kk*16 + tg*2;
        bf[0] = *(const uint32_t*)(kp);
        bf[1] = *(const uint32_t*)(kp + 8);
        mma16(sacc[nt], af, bf);
      }
    }

    int q0 = qr0 + g, q1 = q0 + 8;
    float mx0 = -1e30f, mx1 = -1e30f;
    #pragma unroll
    for (int nt = 0; nt < 8; nt++){
      int c = kt*64 + nt*8 + tg*2;
      sacc[nt][0] = (c     <= q0) ? sacc[nt][0]*SCL : -1e30f;
      sacc[nt][1] = (c + 1 <= q0) ? sacc[nt][1]*SCL : -1e30f;
      sacc[nt][2] = (c     <= q1) ? sacc[nt][2]*SCL : -1e30f;
      sacc[nt][3] = (c + 1 <= q1) ? sacc[nt][3]*SCL : -1e30f;
      mx0 = fmaxf(mx0, fmaxf(sacc[nt][0], sacc[nt][1]));
      mx1 = fmaxf(mx1, fmaxf(sacc[nt][2], sacc[nt][3]));
    }
    mx0 = fmaxf(mx0, __shfl_xor_sync(~0u, mx0, 1));
    mx0 = fmaxf(mx0, __shfl_xor_sync(~0u, mx0, 2));
    mx1 = fmaxf(mx1, __shfl_xor_sync(~0u, mx1, 1));
    mx1 = fmaxf(mx1, __shfl_xor_sync(~0u, mx1, 2));
    float nm0 = fmaxf(m0, mx0), nm1 = fmaxf(m1, mx1);
    float al0 = __expf(m0 - nm0), al1 = __expf(m1 - nm1);
    float s0 = 0.f, s1 = 0.f;
    __half* Pw = Ps + warp*(16*SP);
    #pragma unroll
    for (int nt = 0; nt < 8; nt++){
      float p0 = __expf(sacc[nt][0] - nm0), p1 = __expf(sacc[nt][1] - nm0);
      float p2 = __expf(sacc[nt][2] - nm1), p3 = __expf(sacc[nt][3] - nm1);
      s0 += p0 + p1; s1 += p2 + p3;
      __half* pp = Pw + g*SP + nt*8 + tg*2;
      *(__half2*)(pp)          = __floats2half2_rn(p0, p1);
      *(__half2*)(pp + 8*SP)   = __floats2half2_rn(p2, p3);
    }
    s0 += __shfl_xor_sync(~0u, s0, 1); s0 += __shfl_xor_sync(~0u, s0, 2);
    s1 += __shfl_xor_sync(~0u, s1, 1); s1 += __shfl_xor_sync(~0u, s1, 2);
    l0 = l0*al0 + s0; l1 = l1*al1 + s1;
    m0 = nm0; m1 = nm1;
    #pragma unroll
    for (int nt = 0; nt < 16; nt++){
      o[nt][0] *= al0; o[nt][1] *= al0; o[nt][2] *= al1; o[nt][3] *= al1;
    }
    __syncwarp();

    #pragma unroll
    for (int kk = 0; kk < 4; kk++){
      uint32_t af[4];
      const __half* ap = Pw + g*SP + kk*16 + tg*2;
      af[0] = *(const uint32_t*)(ap);
      af[1] = *(const uint32_t*)(ap + 8*SP);
      af[2] = *(const uint32_t*)(ap + 8);
      af[3] = *(const uint32_t*)(ap + 8*SP + 8);
      #pragma unroll
      for (int nt = 0; nt < 16; nt++){
        uint32_t bf[2];
        const __half* vp = Vtb + (nt*8 + g)*SV + kk*16 + tg*2;
        bf[0] = *(const uint32_t*)(vp);
        bf[1] = *(const uint32_t*)(vp + 8);
        mma16(o[nt], af, bf);
      }
    }
    __syncwarp();
  }

  float i0 = 1.0f / l0, i1 = 1.0f / l1;
  int t0 = qr0 + g;
  __half* ob0 = outp + (size_t)(b*TLEN + t0)*DIM + h*HD;
  __half* ob1 = outp + (size_t)(b*TLEN + t0 + 8)*DIM + h*HD;
  #pragma unroll
  for (int nt = 0; nt < 16; nt++){
    int c = nt*8 + tg*2;
    *(__half2*)(ob0 + c) = __floats2half2_rn(o[nt][0]*i0, o[nt][1]*i0);
    *(__half2*)(ob1 + c) = __floats2half2_rn(o[nt][2]*i1, o[nt][3]*i1);
  }
}

// ---------------- driver ----------------
extern "C" void kernel_launch(void* const* d_in, const int* in_sizes, int n_in,
                              void* d_out, int out_size) {
  (void)in_sizes; (void)n_in; (void)out_size;
  const float* x       = (const float*)d_in[0];
  const float* qkv_w   = (const float*)d_in[1];
  const float* o_w     = (const float*)d_in[2];
  const float* o_scale = (const float*)d_in[3];
  const float* w1      = (const float*)d_in[4];
  const float* w2      = (const float*)d_in[5];
  const float* mscale  = (const float*)d_in[6];
  float* out   = (float*)d_out;
  float* out_x = out;
  float* out_k = out + (size_t)ROWS*DIM;
  float* out_v = out + 2*(size_t)ROWS*DIM;

  float *qkvb; __half *xnh, *attnh, *hh, *wqkvh, *owh, *w1h, *w2h; float2* trig;
  cudaGetSymbolAddress((void**)&qkvb,  g_qkv);
  cudaGetSymbolAddress((void**)&xnh,   g_xnh);
  cudaGetSymbolAddress((void**)&attnh, g_attnh);
  cudaGetSymbolAddress((void**)&hh,    g_hh);
  cudaGetSymbolAddress((void**)&wqkvh, g_wqkvh);
  cudaGetSymbolAddress((void**)&owh,   g_owh);
  cudaGetSymbolAddress((void**)&w1h,   g_w1h);
  cudaGetSymbolAddress((void**)&w2h,   g_w2h);
  cudaGetSymbolAddress((void**)&trig,  g_trig);

  const int GEMM_SMEM = 3*(128 + 256)*72*2;         // 165888 bytes
  const int ATTN_SMEM = (128*136 + 2*64*136 + 2*128*72 + 8*16*72) * 2;  // 124928 bytes
  cudaFuncSetAttribute(hgemm<0>, cudaFuncAttributeMaxDynamicSharedMemorySize, GEMM_SMEM);
  cudaFuncSetAttribute(hgemm<1>, cudaFuncAttributeMaxDynamicSharedMemorySize, GEMM_SMEM);
  cudaFuncSetAttribute(hgemm<2>, cudaFuncAttributeMaxDynamicSharedMemorySize, GEMM_SMEM);
  cudaFuncSetAttribute(attn_k,   cudaFuncAttributeMaxDynamicSharedMemorySize, ATTN_SMEM);

  // 0. trig table + weight conversions fp32 -> fp16
  trig_k<<<TLEN*32/256, 256>>>(trig);
  f2h_k<<<(3*DIM*DIM/4 + 255)/256, 256>>>((const float4*)qkv_w, (__half2*)wqkvh, 3*DIM*DIM/4);
  f2h_k<<<(DIM*DIM/4   + 255)/256, 256>>>((const float4*)o_w,   (__half2*)owh,   DIM*DIM/4);
  f2h_k<<<(4*DIM*DIM/4 + 255)/256, 256>>>((const float4*)w1,    (__half2*)w1h,   4*DIM*DIM/4);
  f2h_k<<<(4*DIM*DIM/4 + 255)/256, 256>>>((const float4*)w2,    (__half2*)w2h,   4*DIM*DIM/4);

  // 1. rmsnorm(x) -> xnh (half)
  rmsnorm_k<<<ROWS, 256>>>(x, xnh);
  // 2a. [q,k] = xnh @ wqkvh[0:2D]^T -> qkvb (stride 2*DIM)  [8192 x 4096]
  hgemm<0><<<dim3(2*DIM/256, ROWS/128), 256, GEMM_SMEM>>>(xnh, wqkvh, qkvb, ROWS, 2*DIM, DIM, nullptr, nullptr);
  // 2b. v = xnh @ wqkvh[2D:3D]^T -> out_v DIRECTLY  [8192 x 2048]
  hgemm<0><<<dim3(DIM/256, ROWS/128), 256, GEMM_SMEM>>>(xnh, wqkvh + (size_t)2*DIM*DIM, out_v, ROWS, DIM, DIM, nullptr, nullptr);
  // 3. QK-norm + rotary: q in place, k -> out_k only
  qkrot_k<<<ROWS, 256>>>(qkvb, trig, out_k);
  // 4. causal attention -> attnh (half)
  attn_k<<<dim3(TLEN/128, NB*NH), 256, ATTN_SMEM>>>(qkvb, out_k, out_v, attnh);
  // 5. x1 = x + (attnh @ owh^T) * o_scale  -> out_x (fp32)
  hgemm<1><<<dim3(DIM/256, ROWS/128), 256, GEMM_SMEM>>>(attnh, owh, out_x, ROWS, DIM, DIM, x, o_scale);
  // 6. rmsnorm(x1) -> xnh
  rmsnorm_k<<<ROWS, 256>>>(out_x, xnh);
  // 7. h = rn(relu(xnh @ w1h^T)^2)  -> hh (half)  [8192 x 8192]
  hgemm<2><<<dim3(4*DIM/256, ROWS/128), 256, GEMM_SMEM>>>(xnh, w1h, hh, ROWS, 4*DIM, DIM, nullptr, nullptr);
  // 8. x_out = x1 + (hh @ w2h^T) * mlp_scale  -> out_x (in place)
  hgemm<1><<<dim3(DIM/256, ROWS/128), 256, GEMM_SMEM>>>(hh, w2h, out_x, ROWS, DIM, 4*DIM, out_x, mscale);
}

// round 17
// speedup vs baseline: 1.5552x; 1.0049x over previous
#include <cuda_runtime.h>
#include <cuda_fp16.h>
#include <cstdint>
#include <math.h>

#define DIM 2048
#define TLEN 2048
#define NB 4
#define HD 128
#define NH 16
#define ROWS (NB*TLEN)   // 8192

// ---------------- scratch (device globals; no allocations allowed) ----------------
__device__ float  g_qkv[(size_t)ROWS*2*DIM];       // fp32 q,k (GEMM 2a output; qkrot input)
__device__ __half g_qh[(size_t)ROWS*DIM];          // rotated q (half)
__device__ __half g_kh[(size_t)ROWS*DIM];          // rotated k (half)
__device__ __half g_vh[(size_t)ROWS*DIM];          // v (half, emitted by GEMM 2b epilogue)
__device__ __half g_xnh[(size_t)ROWS*DIM];         // normalized activations (half)
__device__ __half g_attnh[(size_t)ROWS*DIM];       // attention output (half)
__device__ __half g_hh[(size_t)ROWS*4*DIM];        // mlp hidden (half)
__device__ __half g_wqkvh[(size_t)3*DIM*DIM];      // half weights
__device__ __half g_owh[(size_t)DIM*DIM];
__device__ __half g_w1h[(size_t)4*DIM*DIM];
__device__ __half g_w2h[(size_t)4*DIM*DIM];
__device__ float2 g_trig[(size_t)TLEN*32];         // (cos,sin) per (t, freq-lane)

// ---------------- helpers ----------------
__device__ __forceinline__ void cp16h(__half* s, const __half* g){
  uint32_t sa = (uint32_t)__cvta_generic_to_shared(s);
  asm volatile("cp.async.cg.shared.global [%0], [%1], 16;\n" :: "r"(sa), "l"(g));
}
__device__ __forceinline__ void cp_commit(){ asm volatile("cp.async.commit_group;\n" ::: "memory"); }
template<int N> __device__ __forceinline__ void cp_wait(){
  asm volatile("cp.async.wait_group %0;\n" :: "n"(N) : "memory");
}

// fp16 mma: D(16x8,f32) += A(16x16,f16,row) * B(16x8,f16,col)
__device__ __forceinline__ void mma16(float* d, const uint32_t* a, const uint32_t* b){
  asm volatile(
    "mma.sync.aligned.m16n8k16.row.col.f32.f16.f16.f32 "
    "{%0,%1,%2,%3}, {%4,%5,%6,%7}, {%8,%9}, {%0,%1,%2,%3};\n"
    : "+f"(d[0]), "+f"(d[1]), "+f"(d[2]), "+f"(d[3])
    : "r"(a[0]), "r"(a[1]), "r"(a[2]), "r"(a[3]), "r"(b[0]), "r"(b[1]));
}

__device__ __forceinline__ void ldsm4(uint32_t* r, uint32_t addr){
  asm volatile("ldmatrix.sync.aligned.m8n8.x4.shared.b16 {%0,%1,%2,%3}, [%4];"
    : "=r"(r[0]), "=r"(r[1]), "=r"(r[2]), "=r"(r[3]) : "r"(addr));
}

// ---------------- rotary trig table (computed once; same bits as before) ----------------
__global__ void __launch_bounds__(256) trig_k(float2* __restrict__ tb){
  int i = blockIdx.x * 256 + threadIdx.x;       // 65536 entries
  int t = i >> 5, l = i & 31;
  double fd = pow(1.0e-4, (double)l * (1.0/31.0));
  float thf = (float)t * (float)fd;
  tb[i] = make_float2((float)cos((double)thf), (float)sin((double)thf));
}

// ---------------- fp32 -> fp16 bulk convert ----------------
__global__ void __launch_bounds__(256) f2h_k(const float4* __restrict__ in,
                                             __half2* __restrict__ out, int n4){
  int i = blockIdx.x * 256 + threadIdx.x;
  if (i < n4){
    float4 v = in[i];
    out[2*i]   = __floats2half2_rn(v.x, v.y);
    out[2*i+1] = __floats2half2_rn(v.z, v.w);
  }
}

// ---------------- RMSNorm over last dim (2048), half output ----------------
__global__ void __launch_bounds__(256) rmsnorm_k(const float* __restrict__ x, __half* __restrict__ o){
  __shared__ float red[256];
  size_t base = (size_t)blockIdx.x * DIM;
  const float4* xv = (const float4*)(x + base);
  __half2* ov = (__half2*)(o + base);
  int tid = threadIdx.x;
  float4 a = xv[tid], b = xv[tid + 256];
  float ss = a.x*a.x + a.y*a.y + a.z*a.z + a.w*a.w
           + b.x*b.x + b.y*b.y + b.z*b.z + b.w*b.w;
  red[tid] = ss;
  __syncthreads();
  #pragma unroll
  for (int s = 128; s > 0; s >>= 1){
    if (tid < s) red[tid] += red[tid + s];
    __syncthreads();
  }
  float sc = 1.0f / sqrtf(red[0] * (1.0f/DIM) + 1e-6f);
  ov[2*tid]       = __floats2half2_rn(a.x*sc, a.y*sc);
  ov[2*tid+1]     = __floats2half2_rn(a.z*sc, a.w*sc);
  ov[2*(tid+256)]   = __floats2half2_rn(b.x*sc, b.y*sc);
  ov[2*(tid+256)+1] = __floats2half2_rn(b.z*sc, b.w*sc);
}

// ---------------- QK head-norm + rotary: q -> qh (half), k -> out_k (fp32) + kh (half) ----------------
__global__ void __launch_bounds__(256) qkrot_k(const float* __restrict__ qkv,
                                               const float2* __restrict__ trig,
                                               __half* __restrict__ qh,
                                               __half* __restrict__ kh,
                                               float* __restrict__ out_k){
  int row = blockIdx.x;
  int t = row & (TLEN - 1);
  int tid = threadIdx.x, w = tid >> 5, l = tid & 31;

  float2 cssn = trig[(t << 5) | l];
  float cs = cssn.x, sn = cssn.y;

  const float* base = qkv + (size_t)row * (2*DIM);
  for (int hh = w; hh < 32; hh += 8){
    int isk = (hh >= 16);
    int h = hh & 15;
    const float* p = base + (isk ? DIM : 0) + h*HD;
    float x0 = p[l], x1 = p[l+32], x2 = p[l+64], x3 = p[l+96];
    float ss = x0*x0 + x1*x1 + x2*x2 + x3*x3;
    #pragma unroll
    for (int o = 16; o; o >>= 1) ss += __shfl_xor_sync(~0u, ss, o);
    float sc = 1.0f / sqrtf(ss * (1.0f/HD) + 1e-6f);
    x0 *= sc; x1 *= sc; x2 *= sc; x3 *= sc;
    float y0 =  x0*cs + x2*sn;
    float y2 = -x0*sn + x2*cs;
    __half* dh = (isk ? kh : qh) + (size_t)row*DIM + h*HD;
    dh[l]    = __float2half_rn(y0);
    dh[l+32] = __float2half_rn(x1);
    dh[l+64] = __float2half_rn(y2);
    dh[l+96] = __float2half_rn(x3);
    if (isk){
      float* ok = out_k + (size_t)row*DIM + h*HD;
      ok[l] = y0; ok[l+32] = x1; ok[l+64] = y2; ok[l+96] = x3;
    }
  }
}

// ---------------- fp16 GEMM: C[M,N] = A[M,K] @ B[N,K]^T ----------------
// CTA tile 128x256, 8 warps 2x4, warp tile 64x64. K-stage 64, 3-buffer cp.async ring,
// lookahead 2, ONE __syncthreads per stage, ldmatrix fragment loads.
// EPI 0: fp32 store. EPI 1: fp32 C = res + acc*svec[col]. EPI 2: half C = rn(relu(acc)^2)
// EPI 3: fp32 store to C AND half store to Ch.
template<int EPI>
__global__ void __launch_bounds__(256, 1) hgemm(
    const __half* __restrict__ A, const __half* __restrict__ B, void* __restrict__ Cv,
    int M, int N, int K, const float* __restrict__ res, const float* __restrict__ svec,
    __half* __restrict__ Ch)
{
  extern __shared__ __half smh[];
  const int SH = 72;                        // half stride: 8 rows span all 32 banks
  __half* As = smh;                         // [3][128][72]
  __half* Bs = smh + 3*128*SH;              // [3][256][72]
  int tid = threadIdx.x;
  int warp = tid >> 5, lane = tid & 31;
  int wm = (warp >> 2) * 64, wn = (warp & 3) * 64;
  int g = lane >> 2, tg = lane & 3;
  int bm = blockIdx.y * 128, bn = blockIdx.x * 256;
  const __half* gA = A + (size_t)bm * K;
  const __half* gB = B + (size_t)bn * K;
  int lrow = tid >> 3, lseg = (tid & 7) * 8;

  uint32_t sA = (uint32_t)__cvta_generic_to_shared(As);
  uint32_t sB = sA + 3*128*SH*2;
  uint32_t a_row  = (lane & 7) + ((lane >> 3) & 1) * 8;
  uint32_t a_koff = (lane >> 4) * 8;
  uint32_t b_row  = (lane & 7) + (lane >> 4) * 8;
  uint32_t b_koff = ((lane >> 3) & 1) * 8;
  uint32_t awo = (uint32_t)(wm + a_row) * (SH*2) + a_koff*2;
  uint32_t bwo = (uint32_t)(wn + b_row) * (SH*2) + b_koff*2;

  float acc[4][8][4];
  #pragma unroll
  for (int i = 0; i < 4; i++)
    #pragma unroll
    for (int j = 0; j < 8; j++)
      #pragma unroll
      for (int q = 0; q < 4; q++) acc[i][j][q] = 0.f;

  auto load_stage = [&](int s, int buf){
    int k0 = s * 64;
    __half* as = As + buf * (128*SH);
    __half* bs = Bs + buf * (256*SH);
    #pragma unroll
    for (int i = 0; i < 4; i++){
      int r = lrow + i*32;
      cp16h(as + r*SH + lseg, gA + (size_t)r*K + k0 + lseg);
    }
    #pragma unroll
    for (int i = 0; i < 8; i++){
      int r = lrow + i*32;
      cp16h(bs + r*SH + lseg, gB + (size_t)r*K + k0 + lseg);
    }
  };

  int S = K / 64;
  load_stage(0, 0); cp_commit();
  load_stage(1, 1); cp_commit();

  int buf = 0, nb = 2;
  for (int s = 0; s < S; s++){
    if (s + 1 < S) cp_wait<1>(); else cp_wait<0>();
    __syncthreads();
    if (s + 2 < S){
      load_stage(s + 2, nb);
      cp_commit();
    }
    uint32_t aw = sA + (uint32_t)buf*(128*SH*2) + awo;
    uint32_t bw = sB + (uint32_t)buf*(256*SH*2) + bwo;
    #pragma unroll
    for (int kk = 0; kk < 4; kk++){
      uint32_t af[4][4], bf[8][2];
      #pragma unroll
      for (int mt = 0; mt < 4; mt++)
        ldsm4(af[mt], aw + (uint32_t)mt*(16*SH*2) + kk*32);
      #pragma unroll
      for (int p = 0; p < 4; p++){
        uint32_t r[4];
        ldsm4(r, bw + (uint32_t)p*(16*SH*2) + kk*32);
        bf[2*p][0]   = r[0]; bf[2*p][1]   = r[1];
        bf[2*p+1][0] = r[2]; bf[2*p+1][1] = r[3];
      }
      #pragma unroll
      for (int mt = 0; mt < 4; mt++)
        #pragma unroll
        for (int nt = 0; nt < 8; nt++)
          mma16(acc[mt][nt], af[mt], bf[nt]);
    }
    buf = (buf + 1) % 3;
    nb  = (nb + 1) % 3;
  }

  // epilogue
  #pragma unroll
  for (int mt = 0; mt < 4; mt++){
    int r0 = bm + wm + mt*16 + g;
    #pragma unroll
    for (int nt = 0; nt < 8; nt++){
      int c0 = bn + wn + nt*8 + tg*2;
      float a0 = acc[mt][nt][0], a1 = acc[mt][nt][1];
      float a2 = acc[mt][nt][2], a3 = acc[mt][nt][3];
      if (EPI == 0){
        float* C = (float*)Cv;
        *(float2*)(C + (size_t)r0*N + c0)     = make_float2(a0, a1);
        *(float2*)(C + (size_t)(r0+8)*N + c0) = make_float2(a2, a3);
      } else if (EPI == 1){
        float* C = (float*)Cv;
        float s0 = svec[c0], s1 = svec[c0+1];
        const float* rr0 = res + (size_t)r0*N + c0;
        const float* rr1 = res + (size_t)(r0+8)*N + c0;
        *(float2*)(C + (size_t)r0*N + c0)     = make_float2(rr0[0] + a0*s0, rr0[1] + a1*s1);
        *(float2*)(C + (size_t)(r0+8)*N + c0) = make_float2(rr1[0] + a2*s0, rr1[1] + a3*s1);
      } else if (EPI == 2){
        __half* C = (__half*)Cv;
        float v0 = fmaxf(a0, 0.f), v1 = fmaxf(a1, 0.f);
        float v2 = fmaxf(a2, 0.f), v3 = fmaxf(a3, 0.f);
        *(__half2*)(C + (size_t)r0*N + c0)     = __floats2half2_rn(v0*v0, v1*v1);
        *(__half2*)(C + (size_t)(r0+8)*N + c0) = __floats2half2_rn(v2*v2, v3*v3);
      } else {
        float* C = (float*)Cv;
        *(float2*)(C + (size_t)r0*N + c0)     = make_float2(a0, a1);
        *(float2*)(C + (size_t)(r0+8)*N + c0) = make_float2(a2, a3);
        *(__half2*)(Ch + (size_t)r0*N + c0)     = __floats2half2_rn(a0, a1);
        *(__half2*)(Ch + (size_t)(r0+8)*N + c0) = __floats2half2_rn(a2, a3);
      }
    }
  }
}

// ---------------- causal flash attention (fp16 mma), Qtile=128, Ktile=64 ----------------
// q/k/v all half (stride DIM). Register-prefetch + double-buffered K/V smem tiles.
__global__ void __launch_bounds__(256) attn_k(const __half* __restrict__ qh,
                                              const __half* __restrict__ kh,
                                              const __half* __restrict__ vh,
                                              __half* __restrict__ outp)
{
  extern __shared__ __half smah[];
  const int SQ = 136, SV = 72, SP = 72;
  __half* Qs = smah;                        // 128*136
  __half* Ks = Qs + 128*SQ;                 // 2 x 64*136
  __half* Vt = Ks + 2*64*SQ;                // 2 x 128*72  [d][key]
  __half* Ps = Vt + 2*128*SV;               // 8*16*72
  int tid = threadIdx.x, warp = tid >> 5, lane = tid & 31;
  int g = lane >> 2, tg = lane & 3;
  int qt = blockIdx.x;
  int bh = blockIdx.y; int b = bh >> 4, h = bh & 15;

  // load Q tile (half source, uint4 = 8 halves)
  const __half* qbase = qh + (size_t)(b*TLEN + qt*128)*DIM + h*HD;
  for (int i = tid; i < 128*16; i += 256){
    int r = i >> 4, s8 = (i & 15) * 8;
    *(uint4*)(Qs + r*SQ + s8) = *(const uint4*)(qbase + (size_t)r*DIM + s8);
  }

  float o[16][4];
  #pragma unroll
  for (int i = 0; i < 16; i++){ o[i][0]=0.f; o[i][1]=0.f; o[i][2]=0.f; o[i][3]=0.f; }
  float m0 = -1e30f, m1 = -1e30f, l0 = 0.f, l1 = 0.f;
  int ktn = 2*qt + 2;
  int qr0 = qt*128 + warp*16;
  const float SCL = 0.08838834764831845f;

  // register prefetch staging (half): K tile 64x128h = 1024 uint4, V same
  uint4 kreg[4];
  uint4 vreg[2][2];
  auto load_tile = [&](int kt){
    const __half* kb = kh + (size_t)(b*TLEN + kt*64)*DIM + h*HD;
    const __half* vb = vh + (size_t)(b*TLEN + kt*64)*DIM + h*HD;
    #pragma unroll
    for (int u = 0; u < 4; u++){
      int i = tid + u*256;
      int r = i >> 4, c8 = (i & 15) * 8;
      kreg[u] = *(const uint4*)(kb + (size_t)r*DIM + c8);
    }
    #pragma unroll
    for (int u = 0; u < 2; u++){
      int i = tid + u*256;
      int p = i >> 4, cg = i & 15;          // row-pair p (0..31), col-group cg (0..15)
      int r0 = 2*p, c8 = cg*8;
      vreg[u][0] = *(const uint4*)(vb + (size_t)r0*DIM + c8);
      vreg[u][1] = *(const uint4*)(vb + (size_t)(r0+1)*DIM + c8);
    }
  };
  auto store_tile = [&](int bi){
    __half* Ksb = Ks + bi*(64*SQ);
    __half* Vtb = Vt + bi*(128*SV);
    #pragma unroll
    for (int u = 0; u < 4; u++){
      int i = tid + u*256;
      int r = i >> 4, c8 = (i & 15) * 8;
      *(uint4*)(Ksb + r*SQ + c8) = kreg[u];
    }
    #pragma unroll
    for (int u = 0; u < 2; u++){
      int i = tid + u*256;
      int p = i >> 4, cg = i & 15;
      int r0 = 2*p, c8 = cg*8;
      const __half* h0 = (const __half*)&vreg[u][0];
      const __half* h1 = (const __half*)&vreg[u][1];
      #pragma unroll
      for (int j = 0; j < 8; j++){
        int jj = (j + (tid & 31)) & 7;      // stagger to spread banks
        *(__half2*)(Vtb + (c8 + jj)*SV + r0) = __halves2half2(h0[jj], h1[jj]);
      }
    }
  };

  load_tile(0);
  for (int kt = 0; kt < ktn; kt++){
    int bi = kt & 1;
    // Race-safety: buf bi was last READ by compute(kt-2), retired before iteration
    // (kt-1)'s __syncthreads. Compute(kt-1) reads buf bi^1 — disjoint. One sync/iter.
    store_tile(bi);
    __syncthreads();
    if (kt + 1 < ktn) load_tile(kt + 1);   // overlap gmem latency with compute below
    if (kt*64 > qr0 + 15) continue;

    const __half* Ksb = Ks + bi*(64*SQ);
    const __half* Vtb = Vt + bi*(128*SV);

    float sacc[8][4];
    #pragma unroll
    for (int nt = 0; nt < 8; nt++){ sacc[nt][0]=0.f; sacc[nt][1]=0.f; sacc[nt][2]=0.f; sacc[nt][3]=0.f; }
    #pragma unroll
    for (int kk = 0; kk < 8; kk++){
      uint32_t af[4];
      const __half* qp = Qs + (warp*16 + g)*SQ + kk*16 + tg*2;
      af[0] = *(const uint32_t*)(qp);
      af[1] = *(const uint32_t*)(qp + 8*SQ);
      af[2] = *(const uint32_t*)(qp + 8);
      af[3] = *(const uint32_t*)(qp + 8*SQ + 8);
      #pragma unroll
      for (int nt = 0; nt < 8; nt++){
        uint32_t bf[2];
        const __half* kp = Ksb + (nt*8 + g)*SQ + kk*16 + tg*2;
        bf[0] = *(const uint32_t*)(kp);
        bf[1] = *(const uint32_t*)(kp + 8);
        mma16(sacc[nt], af, bf);
      }
    }

    int q0 = qr0 + g, q1 = q0 + 8;
    float mx0 = -1e30f, mx1 = -1e30f;
    #pragma unroll
    for (int nt = 0; nt < 8; nt++){
      int c = kt*64 + nt*8 + tg*2;
      sacc[nt][0] = (c     <= q0) ? sacc[nt][0]*SCL : -1e30f;
      sacc[nt][1] = (c + 1 <= q0) ? sacc[nt][1]*SCL : -1e30f;
      sacc[nt][2] = (c     <= q1) ? sacc[nt][2]*SCL : -1e30f;
      sacc[nt][3] = (c + 1 <= q1) ? sacc[nt][3]*SCL : -1e30f;
      mx0 = fmaxf(mx0, fmaxf(sacc[nt][0], sacc[nt][1]));
      mx1 = fmaxf(mx1, fmaxf(sacc[nt][2], sacc[nt][3]));
    }
    mx0 = fmaxf(mx0, __shfl_xor_sync(~0u, mx0, 1));
    mx0 = fmaxf(mx0, __shfl_xor_sync(~0u, mx0, 2));
    mx1 = fmaxf(mx1, __shfl_xor_sync(~0u, mx1, 1));
    mx1 = fmaxf(mx1, __shfl_xor_sync(~0u, mx1, 2));
    float nm0 = fmaxf(m0, mx0), nm1 = fmaxf(m1, mx1);
    float al0 = __expf(m0 - nm0), al1 = __expf(m1 - nm1);
    float s0 = 0.f, s1 = 0.f;
    __half* Pw = Ps + warp*(16*SP);
    #pragma unroll
    for (int nt = 0; nt < 8; nt++){
      float p0 = __expf(sacc[nt][0] - nm0), p1 = __expf(sacc[nt][1] - nm0);
      float p2 = __expf(sacc[nt][2] - nm1), p3 = __expf(sacc[nt][3] - nm1);
      s0 += p0 + p1; s1 += p2 + p3;
      __half* pp = Pw + g*SP + nt*8 + tg*2;
      *(__half2*)(pp)          = __floats2half2_rn(p0, p1);
      *(__half2*)(pp + 8*SP)   = __floats2half2_rn(p2, p3);
    }
    s0 += __shfl_xor_sync(~0u, s0, 1); s0 += __shfl_xor_sync(~0u, s0, 2);
    s1 += __shfl_xor_sync(~0u, s1, 1); s1 += __shfl_xor_sync(~0u, s1, 2);
    l0 = l0*al0 + s0; l1 = l1*al1 + s1;
    m0 = nm0; m1 = nm1;
    #pragma unroll
    for (int nt = 0; nt < 16; nt++){
      o[nt][0] *= al0; o[nt][1] *= al0; o[nt][2] *= al1; o[nt][3] *= al1;
    }
    __syncwarp();

    #pragma unroll
    for (int kk = 0; kk < 4; kk++){
      uint32_t af[4];
      const __half* ap = Pw + g*SP + kk*16 + tg*2;
      af[0] = *(const uint32_t*)(ap);
      af[1] = *(const uint32_t*)(ap + 8*SP);
      af[2] = *(const uint32_t*)(ap + 8);
      af[3] = *(const uint32_t*)(ap + 8*SP + 8);
      #pragma unroll
      for (int nt = 0; nt < 16; nt++){
        uint32_t bf[2];
        const __half* vp = Vtb + (nt*8 + g)*SV + kk*16 + tg*2;
        bf[0] = *(const uint32_t*)(vp);
        bf[1] = *(const uint32_t*)(vp + 8);
        mma16(o[nt], af, bf);
      }
    }
    __syncwarp();
  }

  float i0 = 1.0f / l0, i1 = 1.0f / l1;
  int t0 = qr0 + g;
  __half* ob0 = outp + (size_t)(b*TLEN + t0)*DIM + h*HD;
  __half* ob1 = outp + (size_t)(b*TLEN + t0 + 8)*DIM + h*HD;
  #pragma unroll
  for (int nt = 0; nt < 16; nt++){
    int c = nt*8 + tg*2;
    *(__half2*)(ob0 + c) = __floats2half2_rn(o[nt][0]*i0, o[nt][1]*i0);
    *(__half2*)(ob1 + c) = __floats2half2_rn(o[nt][2]*i1, o[nt][3]*i1);
  }
}

// ---------------- driver ----------------
extern "C" void kernel_launch(void* const* d_in, const int* in_sizes, int n_in,
                              void* d_out, int out_size) {
  (void)in_sizes; (void)n_in; (void)out_size;
  const float* x       = (const float*)d_in[0];
  const float* qkv_w   = (const float*)d_in[1];
  const float* o_w     = (const float*)d_in[2];
  const float* o_scale = (const float*)d_in[3];
  const float* w1      = (const float*)d_in[4];
  const float* w2      = (const float*)d_in[5];
  const float* mscale  = (const float*)d_in[6];
  float* out   = (float*)d_out;
  float* out_x = out;
  float* out_k = out + (size_t)ROWS*DIM;
  float* out_v = out + 2*(size_t)ROWS*DIM;

  float *qkvb; __half *qhp, *khp, *vhp, *xnh, *attnh, *hh, *wqkvh, *owh, *w1h, *w2h; float2* trig;
  cudaGetSymbolAddress((void**)&qkvb,  g_qkv);
  cudaGetSymbolAddress((void**)&qhp,   g_qh);
  cudaGetSymbolAddress((void**)&khp,   g_kh);
  cudaGetSymbolAddress((void**)&vhp,   g_vh);
  cudaGetSymbolAddress((void**)&xnh,   g_xnh);
  cudaGetSymbolAddress((void**)&attnh, g_attnh);
  cudaGetSymbolAddress((void**)&hh,    g_hh);
  cudaGetSymbolAddress((void**)&wqkvh, g_wqkvh);
  cudaGetSymbolAddress((void**)&owh,   g_owh);
  cudaGetSymbolAddress((void**)&w1h,   g_w1h);
  cudaGetSymbolAddress((void**)&w2h,   g_w2h);
  cudaGetSymbolAddress((void**)&trig,  g_trig);

  const int GEMM_SMEM = 3*(128 + 256)*72*2;         // 165888 bytes
  const int ATTN_SMEM = (128*136 + 2*64*136 + 2*128*72 + 8*16*72) * 2;  // 124928 bytes
  cudaFuncSetAttribute(hgemm<0>, cudaFuncAttributeMaxDynamicSharedMemorySize, GEMM_SMEM);
  cudaFuncSetAttribute(hgemm<1>, cudaFuncAttributeMaxDynamicSharedMemorySize, GEMM_SMEM);
  cudaFuncSetAttribute(hgemm<2>, cudaFuncAttributeMaxDynamicSharedMemorySize, GEMM_SMEM);
  cudaFuncSetAttribute(hgemm<3>, cudaFuncAttributeMaxDynamicSharedMemorySize, GEMM_SMEM);
  cudaFuncSetAttribute(attn_k,   cudaFuncAttributeMaxDynamicSharedMemorySize, ATTN_SMEM);

  // 0. trig table + weight conversions fp32 -> fp16
  trig_k<<<TLEN*32/256, 256>>>(trig);
  f2h_k<<<(3*DIM*DIM/4 + 255)/256, 256>>>((const float4*)qkv_w, (__half2*)wqkvh, 3*DIM*DIM/4);
  f2h_k<<<(DIM*DIM/4   + 255)/256, 256>>>((const float4*)o_w,   (__half2*)owh,   DIM*DIM/4);
  f2h_k<<<(4*DIM*DIM/4 + 255)/256, 256>>>((const float4*)w1,    (__half2*)w1h,   4*DIM*DIM/4);
  f2h_k<<<(4*DIM*DIM/4 + 255)/256, 256>>>((const float4*)w2,    (__half2*)w2h,   4*DIM*DIM/4);

  // 1. rmsnorm(x) -> xnh (half)
  rmsnorm_k<<<ROWS, 256>>>(x, xnh);
  // 2a. [q,k] = xnh @ wqkvh[0:2D]^T -> qkvb (stride 2*DIM)  [8192 x 4096]
  hgemm<0><<<dim3(2*DIM/256, ROWS/128), 256, GEMM_SMEM>>>(xnh, wqkvh, qkvb, ROWS, 2*DIM, DIM, nullptr, nullptr, nullptr);
  // 2b. v = xnh @ wqkvh[2D:3D]^T -> out_v (fp32) + g_vh (half)  [8192 x 2048]
  hgemm<3><<<dim3(DIM/256, ROWS/128), 256, GEMM_SMEM>>>(xnh, wqkvh + (size_t)2*DIM*DIM, out_v, ROWS, DIM, DIM, nullptr, nullptr, vhp);
  // 3. QK-norm + rotary: q -> qh (half), k -> out_k (fp32) + kh (half)
  qkrot_k<<<ROWS, 256>>>(qkvb, trig, qhp, khp, out_k);
  // 4. causal attention (all-half inputs) -> attnh (half)
  attn_k<<<dim3(TLEN/128, NB*NH), 256, ATTN_SMEM>>>(qhp, khp, vhp, attnh);
  // 5. x1 = x + (attnh @ owh^T) * o_scale  -> out_x (fp32)
  hgemm<1><<<dim3(DIM/256, ROWS/128), 256, GEMM_SMEM>>>(attnh, owh, out_x, ROWS, DIM, DIM, x, o_scale, nullptr);
  // 6. rmsnorm(x1) -> xnh
  rmsnorm_k<<<ROWS, 256>>>(out_x, xnh);
  // 7. h = rn(relu(xnh @ w1h^T)^2)  -> hh (half)  [8192 x 8192]
  hgemm<2><<<dim3(4*DIM/256, ROWS/128), 256, GEMM_SMEM>>>(xnh, w1h, hh, ROWS, 4*DIM, DIM, nullptr, nullptr, nullptr);
  // 8. x_out = x1 + (hh @ w2h^T) * mlp_scale  -> out_x (in place)
  hgemm<1><<<dim3(DIM/256, ROWS/128), 256, GEMM_SMEM>>>(hh, w2h, out_x, ROWS, DIM, 4*DIM, out_x, mscale, nullptr);
}